// round 1
// baseline (speedup 1.0000x reference)
#include <cuda_runtime.h>
#include <math.h>

#define D_MODEL 2048
#define N_HEADS 16
#define HEAD_DIM 128
#define SEQ 2048
#define BATCH 2
#define MROWS (BATCH*SEQ)   // 4096

// Scratch (static device globals; no allocation allowed)
__device__ float g_q[(size_t)MROWS * D_MODEL];
__device__ float g_k[(size_t)MROWS * D_MODEL];
__device__ float g_v[(size_t)MROWS * D_MODEL];
__device__ float g_o[(size_t)MROWS * D_MODEL];

// ---------------------------------------------------------------------------
// SGEMM NT: C[M,N] = A[M,K] * B[N,K]^T   (both row-major, K-contiguous)
// Block tile 128x128, K-tile 16, 256 threads, 8x8 per thread (4x4 quads).
// ---------------------------------------------------------------------------
__global__ __launch_bounds__(256) void sgemm_nt(const float* __restrict__ A,
                                                const float* __restrict__ B,
                                                float* __restrict__ C,
                                                int M, int N, int K)
{
    __shared__ float As[16][128];
    __shared__ float Bs[16][128];

    const int tid = threadIdx.x;
    const int tx = tid & 15;
    const int ty = tid >> 4;
    const int m0 = blockIdx.y * 128;
    const int n0 = blockIdx.x * 128;

    const float* Ab = A + (size_t)m0 * K;
    const float* Bb = B + (size_t)n0 * K;

    const int lr = tid >> 2;          // 0..63
    const int lk = (tid & 3) << 2;    // 0,4,8,12

    float acc[8][8];
    #pragma unroll
    for (int i = 0; i < 8; i++)
        #pragma unroll
        for (int j = 0; j < 8; j++) acc[i][j] = 0.f;

    for (int kt = 0; kt < K; kt += 16) {
        float4 a0 = *(const float4*)(Ab + (size_t)lr * K + kt + lk);
        float4 a1 = *(const float4*)(Ab + (size_t)(lr + 64) * K + kt + lk);
        float4 b0 = *(const float4*)(Bb + (size_t)lr * K + kt + lk);
        float4 b1 = *(const float4*)(Bb + (size_t)(lr + 64) * K + kt + lk);
        __syncthreads();
        As[lk+0][lr] = a0.x; As[lk+1][lr] = a0.y; As[lk+2][lr] = a0.z; As[lk+3][lr] = a0.w;
        As[lk+0][lr+64] = a1.x; As[lk+1][lr+64] = a1.y; As[lk+2][lr+64] = a1.z; As[lk+3][lr+64] = a1.w;
        Bs[lk+0][lr] = b0.x; Bs[lk+1][lr] = b0.y; Bs[lk+2][lr] = b0.z; Bs[lk+3][lr] = b0.w;
        Bs[lk+0][lr+64] = b1.x; Bs[lk+1][lr+64] = b1.y; Bs[lk+2][lr+64] = b1.z; Bs[lk+3][lr+64] = b1.w;
        __syncthreads();
        #pragma unroll
        for (int kk = 0; kk < 16; kk++) {
            float4 aL = *(const float4*)&As[kk][ty*4];
            float4 aH = *(const float4*)&As[kk][ty*4 + 64];
            float4 bL = *(const float4*)&Bs[kk][tx*4];
            float4 bH = *(const float4*)&Bs[kk][tx*4 + 64];
            float a[8] = {aL.x,aL.y,aL.z,aL.w,aH.x,aH.y,aH.z,aH.w};
            float b[8] = {bL.x,bL.y,bL.z,bL.w,bH.x,bH.y,bH.z,bH.w};
            #pragma unroll
            for (int i = 0; i < 8; i++)
                #pragma unroll
                for (int j = 0; j < 8; j++)
                    acc[i][j] = fmaf(a[i], b[j], acc[i][j]);
        }
    }

    #pragma unroll
    for (int i = 0; i < 8; i++) {
        int r = m0 + ((i < 4) ? (ty*4 + i) : (64 + ty*4 + (i - 4)));
        float4 cL = make_float4(acc[i][0], acc[i][1], acc[i][2], acc[i][3]);
        float4 cH = make_float4(acc[i][4], acc[i][5], acc[i][6], acc[i][7]);
        *(float4*)(C + (size_t)r * N + n0 + tx*4)      = cL;
        *(float4*)(C + (size_t)r * N + n0 + 64 + tx*4) = cH;
    }
}

// ---------------------------------------------------------------------------
// RoPE, in place on Q and K (layout [B*S, D_MODEL]; per head pairs (j, j+64))
// ---------------------------------------------------------------------------
__global__ void rope_kernel(float* __restrict__ Q, float* __restrict__ Kc)
{
    int idx = blockIdx.x * blockDim.x + threadIdx.x;
    if (idx >= MROWS * N_HEADS * 64) return;
    int j   = idx & 63;
    int h   = (idx >> 6) & (N_HEADS - 1);
    int row = idx >> 10;
    int s   = row & (SEQ - 1);

    // inv_freq = 10000^(-j/64) = exp2(-j/64 * log2(10000))
    float inv = exp2f(-(float)j * (13.287712379549449f / 64.0f));
    float ang = (float)s * inv;
    float sn, cs;
    sincosf(ang, &sn, &cs);

    size_t base = (size_t)row * D_MODEL + h * HEAD_DIM + j;
    float q1 = Q[base], q2 = Q[base + 64];
    Q[base]      = q1 * cs - q2 * sn;
    Q[base + 64] = q2 * cs + q1 * sn;
    float k1 = Kc[base], k2 = Kc[base + 64];
    Kc[base]      = k1 * cs - k2 * sn;
    Kc[base + 64] = k2 * cs + k1 * sn;
}

// ---------------------------------------------------------------------------
// Flash attention (fp32, causal). 64 queries x 64 keys per tile, 256 threads.
// Thread (ty,tx): S-tile 4x4 (rows ty*4+i, cols tx*4+j),
//                 O-tile 4x8 (rows ty*4+i, cols tx*4+{0..3} and 64+tx*4+{0..3}).
// ---------------------------------------------------------------------------
#define ATTN_SMEM_BYTES (64*(129+129+128+65)*4)

__global__ __launch_bounds__(256) void attn_kernel(const float* __restrict__ Q,
                                                   const float* __restrict__ K,
                                                   const float* __restrict__ V,
                                                   float* __restrict__ O)
{
    extern __shared__ float sm[];
    float* Qs = sm;                  // 64 x 129 (padded)
    float* Ks = Qs + 64 * 129;       // 64 x 129 (padded)
    float* Vs = Ks + 64 * 129;       // 64 x 128
    float* Ps = Vs + 64 * 128;       // 64 x 65  (padded)

    const int tid = threadIdx.x;
    const int tx = tid & 15;
    const int ty = tid >> 4;
    const int q0 = blockIdx.x * 64;
    const int b  = blockIdx.y >> 4;
    const int h  = blockIdx.y & (N_HEADS - 1);
    const float scale = 0.088388347648318447f;  // 1/sqrt(128)

    const float* Qb = Q + ((size_t)(b * SEQ + q0)) * D_MODEL + h * HEAD_DIM;
    const float* Kb = K + ((size_t)(b * SEQ)) * D_MODEL + h * HEAD_DIM;
    const float* Vb = V + ((size_t)(b * SEQ)) * D_MODEL + h * HEAD_DIM;

    // Load Q tile (pre-scaled)
    for (int p = tid; p < 64 * 32; p += 256) {
        int r = p >> 5, d4 = (p & 31) << 2;
        float4 v = *(const float4*)(Qb + (size_t)r * D_MODEL + d4);
        float* dst = &Qs[r * 129 + d4];
        dst[0] = v.x * scale; dst[1] = v.y * scale;
        dst[2] = v.z * scale; dst[3] = v.w * scale;
    }

    float m_i[4], l_i[4], acc[4][8];
    #pragma unroll
    for (int i = 0; i < 4; i++) {
        m_i[i] = -1e30f; l_i[i] = 0.f;
        #pragma unroll
        for (int j = 0; j < 8; j++) acc[i][j] = 0.f;
    }

    const int ntiles = blockIdx.x + 1;   // causal: keys up to q0+63
    for (int kt = 0; kt < ntiles; kt++) {
        const int k0 = kt * 64;
        __syncthreads();   // previous tile's PV done before overwriting K/V
        for (int p = tid; p < 64 * 32; p += 256) {
            int r = p >> 5, d4 = (p & 31) << 2;
            float4 kv = *(const float4*)(Kb + (size_t)(k0 + r) * D_MODEL + d4);
            float* kd = &Ks[r * 129 + d4];
            kd[0] = kv.x; kd[1] = kv.y; kd[2] = kv.z; kd[3] = kv.w;
            float4 vv = *(const float4*)(Vb + (size_t)(k0 + r) * D_MODEL + d4);
            *(float4*)&Vs[r * 128 + d4] = vv;
        }
        __syncthreads();

        // S = Qs @ Ks^T (scaled already)
        float s_acc[4][4];
        #pragma unroll
        for (int i = 0; i < 4; i++)
            #pragma unroll
            for (int j = 0; j < 4; j++) s_acc[i][j] = 0.f;

        #pragma unroll 4
        for (int d = 0; d < 128; d++) {
            float a[4], bb[4];
            #pragma unroll
            for (int i = 0; i < 4; i++) a[i] = Qs[(ty*4 + i) * 129 + d];
            #pragma unroll
            for (int j = 0; j < 4; j++) bb[j] = Ks[(tx*4 + j) * 129 + d];
            #pragma unroll
            for (int i = 0; i < 4; i++)
                #pragma unroll
                for (int j = 0; j < 4; j++)
                    s_acc[i][j] = fmaf(a[i], bb[j], s_acc[i][j]);
        }

        // Causal mask — only the diagonal tile needs it
        if (kt == ntiles - 1) {
            #pragma unroll
            for (int i = 0; i < 4; i++)
                #pragma unroll
                for (int j = 0; j < 4; j++)
                    if (k0 + tx*4 + j > q0 + ty*4 + i) s_acc[i][j] = -1e30f;
        }

        // Online softmax (row groups of 16 threads)
        #pragma unroll
        for (int i = 0; i < 4; i++) {
            float rm = fmaxf(fmaxf(s_acc[i][0], s_acc[i][1]),
                             fmaxf(s_acc[i][2], s_acc[i][3]));
            #pragma unroll
            for (int off = 8; off > 0; off >>= 1)
                rm = fmaxf(rm, __shfl_xor_sync(0xffffffffu, rm, off, 16));
            float mn = fmaxf(m_i[i], rm);
            float alpha = __expf(m_i[i] - mn);
            float psum = 0.f;
            #pragma unroll
            for (int j = 0; j < 4; j++) {
                float pp = __expf(s_acc[i][j] - mn);
                s_acc[i][j] = pp;
                psum += pp;
            }
            #pragma unroll
            for (int off = 8; off > 0; off >>= 1)
                psum += __shfl_xor_sync(0xffffffffu, psum, off, 16);
            l_i[i] = l_i[i] * alpha + psum;
            m_i[i] = mn;
            #pragma unroll
            for (int j = 0; j < 8; j++) acc[i][j] *= alpha;
            float* pr = &Ps[(ty*4 + i) * 65 + tx*4];
            pr[0] = s_acc[i][0]; pr[1] = s_acc[i][1];
            pr[2] = s_acc[i][2]; pr[3] = s_acc[i][3];
        }
        __syncthreads();

        // O += P @ V
        #pragma unroll 2
        for (int k = 0; k < 64; k++) {
            float a[4];
            #pragma unroll
            for (int i = 0; i < 4; i++) a[i] = Ps[(ty*4 + i) * 65 + k];
            float4 vL = *(const float4*)&Vs[k * 128 + tx*4];
            float4 vH = *(const float4*)&Vs[k * 128 + 64 + tx*4];
            float vv[8] = {vL.x, vL.y, vL.z, vL.w, vH.x, vH.y, vH.z, vH.w};
            #pragma unroll
            for (int i = 0; i < 4; i++)
                #pragma unroll
                for (int j = 0; j < 8; j++)
                    acc[i][j] = fmaf(a[i], vv[j], acc[i][j]);
        }
    }

    // Epilogue: normalize, write to [B*S, H*Dh] layout (transpose-back for free)
    #pragma unroll
    for (int i = 0; i < 4; i++) {
        float inv = 1.0f / l_i[i];
        size_t orow = ((size_t)(b * SEQ + q0 + ty*4 + i)) * D_MODEL + h * HEAD_DIM;
        float4 oL = make_float4(acc[i][0]*inv, acc[i][1]*inv, acc[i][2]*inv, acc[i][3]*inv);
        float4 oH = make_float4(acc[i][4]*inv, acc[i][5]*inv, acc[i][6]*inv, acc[i][7]*inv);
        *(float4*)(O + orow + tx*4)      = oL;
        *(float4*)(O + orow + 64 + tx*4) = oH;
    }
}

// ---------------------------------------------------------------------------
extern "C" void kernel_launch(void* const* d_in, const int* in_sizes, int n_in,
                              void* d_out, int out_size)
{
    const float* X  = (const float*)d_in[0];
    const float* Wq = (const float*)d_in[1];
    const float* Wk = (const float*)d_in[2];
    const float* Wv = (const float*)d_in[3];
    const float* Wo = (const float*)d_in[4];
    float* out = (float*)d_out;

    float *q, *k, *v, *o;
    cudaGetSymbolAddress((void**)&q, g_q);
    cudaGetSymbolAddress((void**)&k, g_k);
    cudaGetSymbolAddress((void**)&v, g_v);
    cudaGetSymbolAddress((void**)&o, g_o);

    cudaFuncSetAttribute(attn_kernel, cudaFuncAttributeMaxDynamicSharedMemorySize,
                         ATTN_SMEM_BYTES);

    dim3 gg(D_MODEL / 128, MROWS / 128);
    dim3 blk(256);

    sgemm_nt<<<gg, blk>>>(X, Wq, q, MROWS, D_MODEL, D_MODEL);
    sgemm_nt<<<gg, blk>>>(X, Wk, k, MROWS, D_MODEL, D_MODEL);
    sgemm_nt<<<gg, blk>>>(X, Wv, v, MROWS, D_MODEL, D_MODEL);

    rope_kernel<<<(MROWS * N_HEADS * 64) / 256, 256>>>(q, k);

    attn_kernel<<<dim3(SEQ / 64, BATCH * N_HEADS), 256, ATTN_SMEM_BYTES>>>(q, k, v, o);

    sgemm_nt<<<gg, blk>>>(o, Wo, out, MROWS, D_MODEL, D_MODEL);
}

// round 2
// speedup vs baseline: 1.8430x; 1.8430x over previous
#include <cuda_runtime.h>
#include <math.h>
#include <stdint.h>

#define D_MODEL 2048
#define N_HEADS 16
#define HEAD_DIM 128
#define SEQ 2048
#define BATCH 2
#define MROWS (BATCH*SEQ)   // 4096

// Scratch (static device globals; no allocation allowed)
__device__ float g_q[(size_t)MROWS * D_MODEL];
__device__ float g_k[(size_t)MROWS * D_MODEL];
__device__ float g_v[(size_t)MROWS * D_MODEL];
__device__ float g_o[(size_t)MROWS * D_MODEL];
__device__ float g_xt[(size_t)MROWS * D_MODEL];          // tf32-rounded X
__device__ float g_wt[4][(size_t)D_MODEL * D_MODEL];     // tf32-rounded Wq,Wk,Wv,Wo

// ---------------------------------------------------------------------------
// helpers
// ---------------------------------------------------------------------------
__device__ __forceinline__ float tf32r(float x) {
    uint32_t u;
    asm("cvt.rna.tf32.f32 %0, %1;" : "=r"(u) : "f"(x));
    return __uint_as_float(u);
}

__global__ void tf32_round(const float4* __restrict__ src, float4* __restrict__ dst, int n4)
{
    int i = blockIdx.x * blockDim.x + threadIdx.x;
    if (i >= n4) return;
    float4 v = src[i];
    v.x = tf32r(v.x); v.y = tf32r(v.y); v.z = tf32r(v.z); v.w = tf32r(v.w);
    dst[i] = v;
}

__device__ __forceinline__ void cpa16(float* s, const float* g) {
    unsigned saddr = (unsigned)__cvta_generic_to_shared(s);
    asm volatile("cp.async.cg.shared.global [%0], [%1], 16;" :: "r"(saddr), "l"(g));
}

// ---------------------------------------------------------------------------
// tf32 tensor-core GEMM NT: C[M,N] = A[M,K] * B[N,K]^T
// A, B must be pre-rounded to tf32. Block 128x128, K-tile 32, 256 threads.
// Warp tile 64x32 via m16n8k8 mma (4x4 tiles).
// ---------------------------------------------------------------------------
#define BM 128
#define BN 128
#define BK 32
#define LDS_STRIDE 36
#define GEMM_SMEM_BYTES (2 * (BM + BN) * LDS_STRIDE * 4)

__global__ __launch_bounds__(256) void gemm_tf32(const float* __restrict__ A,
                                                 const float* __restrict__ B,
                                                 float* __restrict__ C,
                                                 int M, int N, int K)
{
    extern __shared__ float sm[];
    float* As = sm;                          // 2 x [BM][36]
    float* Bs = sm + 2 * BM * LDS_STRIDE;    // 2 x [BN][36]

    const int tid  = threadIdx.x;
    const int warp = tid >> 5;
    const int lane = tid & 31;
    const int wm = (warp >> 2) * 64;   // 0,64
    const int wn = (warp & 3) * 32;    // 0,32,64,96
    const int lr = lane >> 2;          // 0..7
    const int lc = lane & 3;           // 0..3

    const int m0 = blockIdx.y * BM;
    const int n0 = blockIdx.x * BN;

    // loader mapping: 32 rows x 8 float4-cols per pass, 4 passes
    const int ldr = tid >> 3;          // 0..31
    const int ldc = (tid & 7) * 4;     // 0,4,..,28

    float c[4][4][4];
    #pragma unroll
    for (int i = 0; i < 4; i++)
        #pragma unroll
        for (int j = 0; j < 4; j++)
            #pragma unroll
            for (int e = 0; e < 4; e++) c[i][j][e] = 0.f;

    const int nk = K / BK;

    // prologue: tile 0 -> buffer 0
    {
        const float* Ag = A + (size_t)(m0 + ldr) * K + ldc;
        const float* Bg = B + (size_t)(n0 + ldr) * K + ldc;
        float* Asd = As + ldr * LDS_STRIDE + ldc;
        float* Bsd = Bs + ldr * LDS_STRIDE + ldc;
        #pragma unroll
        for (int i = 0; i < 4; i++) {
            cpa16(Asd + 32 * i * LDS_STRIDE, Ag + (size_t)(32 * i) * K);
            cpa16(Bsd + 32 * i * LDS_STRIDE, Bg + (size_t)(32 * i) * K);
        }
        asm volatile("cp.async.commit_group;");
    }

    for (int kt = 0; kt < nk; kt++) {
        asm volatile("cp.async.wait_group 0;");
        __syncthreads();

        if (kt + 1 < nk) {
            const int kb = (kt + 1) * BK;
            const int buf = (kt + 1) & 1;
            const float* Ag = A + (size_t)(m0 + ldr) * K + kb + ldc;
            const float* Bg = B + (size_t)(n0 + ldr) * K + kb + ldc;
            float* Asd = As + buf * BM * LDS_STRIDE + ldr * LDS_STRIDE + ldc;
            float* Bsd = Bs + buf * BN * LDS_STRIDE + ldr * LDS_STRIDE + ldc;
            #pragma unroll
            for (int i = 0; i < 4; i++) {
                cpa16(Asd + 32 * i * LDS_STRIDE, Ag + (size_t)(32 * i) * K);
                cpa16(Bsd + 32 * i * LDS_STRIDE, Bg + (size_t)(32 * i) * K);
            }
            asm volatile("cp.async.commit_group;");
        }

        const uint32_t* as_u = (const uint32_t*)(As + (kt & 1) * BM * LDS_STRIDE);
        const uint32_t* bs_u = (const uint32_t*)(Bs + (kt & 1) * BN * LDS_STRIDE);

        #pragma unroll
        for (int ks = 0; ks < 4; ks++) {
            const int kk = ks * 8;
            uint32_t a[4][4], b[4][2];
            #pragma unroll
            for (int mt = 0; mt < 4; mt++) {
                int base = (wm + mt * 16 + lr) * LDS_STRIDE + kk + lc;
                a[mt][0] = as_u[base];
                a[mt][1] = as_u[base + 8 * LDS_STRIDE];
                a[mt][2] = as_u[base + 4];
                a[mt][3] = as_u[base + 8 * LDS_STRIDE + 4];
            }
            #pragma unroll
            for (int nt = 0; nt < 4; nt++) {
                int base = (wn + nt * 8 + lr) * LDS_STRIDE + kk + lc;
                b[nt][0] = bs_u[base];
                b[nt][1] = bs_u[base + 4];
            }
            #pragma unroll
            for (int mt = 0; mt < 4; mt++)
                #pragma unroll
                for (int nt = 0; nt < 4; nt++) {
                    asm volatile(
                        "mma.sync.aligned.m16n8k8.row.col.f32.tf32.tf32.f32 "
                        "{%0,%1,%2,%3},{%4,%5,%6,%7},{%8,%9},{%0,%1,%2,%3};"
                        : "+f"(c[mt][nt][0]), "+f"(c[mt][nt][1]),
                          "+f"(c[mt][nt][2]), "+f"(c[mt][nt][3])
                        : "r"(a[mt][0]), "r"(a[mt][1]), "r"(a[mt][2]), "r"(a[mt][3]),
                          "r"(b[nt][0]), "r"(b[nt][1]));
                }
        }
    }

    // epilogue
    #pragma unroll
    for (int mt = 0; mt < 4; mt++) {
        #pragma unroll
        for (int nt = 0; nt < 4; nt++) {
            int row = m0 + wm + mt * 16 + lr;
            int col = n0 + wn + nt * 8 + 2 * lc;
            *(float2*)(C + (size_t)row * N + col)       = make_float2(c[mt][nt][0], c[mt][nt][1]);
            *(float2*)(C + (size_t)(row + 8) * N + col) = make_float2(c[mt][nt][2], c[mt][nt][3]);
        }
    }
}

// ---------------------------------------------------------------------------
// RoPE, in place on Q and K (layout [B*S, D_MODEL]; per head pairs (j, j+64))
// ---------------------------------------------------------------------------
__global__ void rope_kernel(float* __restrict__ Q, float* __restrict__ Kc)
{
    int idx = blockIdx.x * blockDim.x + threadIdx.x;
    if (idx >= MROWS * N_HEADS * 64) return;
    int j   = idx & 63;
    int h   = (idx >> 6) & (N_HEADS - 1);
    int row = idx >> 10;
    int s   = row & (SEQ - 1);

    float inv = exp2f(-(float)j * (13.287712379549449f / 64.0f));
    float ang = (float)s * inv;
    float sn, cs;
    sincosf(ang, &sn, &cs);

    size_t base = (size_t)row * D_MODEL + h * HEAD_DIM + j;
    float q1 = Q[base], q2 = Q[base + 64];
    Q[base]      = q1 * cs - q2 * sn;
    Q[base + 64] = q2 * cs + q1 * sn;
    float k1 = Kc[base], k2 = Kc[base + 64];
    Kc[base]      = k1 * cs - k2 * sn;
    Kc[base + 64] = k2 * cs + k1 * sn;
}

// ---------------------------------------------------------------------------
// Flash attention (fp32, causal). 64x64 tiles, 256 threads.
// ---------------------------------------------------------------------------
#define ATTN_SMEM_BYTES (64*(129+129+128+65)*4)

__global__ __launch_bounds__(256) void attn_kernel(const float* __restrict__ Q,
                                                   const float* __restrict__ K,
                                                   const float* __restrict__ V,
                                                   float* __restrict__ O)
{
    extern __shared__ float sm[];
    float* Qs = sm;                  // 64 x 129
    float* Ks = Qs + 64 * 129;       // 64 x 129
    float* Vs = Ks + 64 * 129;       // 64 x 128
    float* Ps = Vs + 64 * 128;       // 64 x 65

    const int tid = threadIdx.x;
    const int tx = tid & 15;
    const int ty = tid >> 4;
    const int q0 = blockIdx.x * 64;
    const int b  = blockIdx.y >> 4;
    const int h  = blockIdx.y & (N_HEADS - 1);
    const float scale = 0.088388347648318447f;  // 1/sqrt(128)

    const float* Qb = Q + ((size_t)(b * SEQ + q0)) * D_MODEL + h * HEAD_DIM;
    const float* Kb = K + ((size_t)(b * SEQ)) * D_MODEL + h * HEAD_DIM;
    const float* Vb = V + ((size_t)(b * SEQ)) * D_MODEL + h * HEAD_DIM;

    for (int p = tid; p < 64 * 32; p += 256) {
        int r = p >> 5, d4 = (p & 31) << 2;
        float4 v = *(const float4*)(Qb + (size_t)r * D_MODEL + d4);
        float* dst = &Qs[r * 129 + d4];
        dst[0] = v.x * scale; dst[1] = v.y * scale;
        dst[2] = v.z * scale; dst[3] = v.w * scale;
    }

    float m_i[4], l_i[4], acc[4][8];
    #pragma unroll
    for (int i = 0; i < 4; i++) {
        m_i[i] = -1e30f; l_i[i] = 0.f;
        #pragma unroll
        for (int j = 0; j < 8; j++) acc[i][j] = 0.f;
    }

    const int ntiles = blockIdx.x + 1;
    for (int kt = 0; kt < ntiles; kt++) {
        const int k0 = kt * 64;
        __syncthreads();
        for (int p = tid; p < 64 * 32; p += 256) {
            int r = p >> 5, d4 = (p & 31) << 2;
            float4 kv = *(const float4*)(Kb + (size_t)(k0 + r) * D_MODEL + d4);
            float* kd = &Ks[r * 129 + d4];
            kd[0] = kv.x; kd[1] = kv.y; kd[2] = kv.z; kd[3] = kv.w;
            float4 vv = *(const float4*)(Vb + (size_t)(k0 + r) * D_MODEL + d4);
            *(float4*)&Vs[r * 128 + d4] = vv;
        }
        __syncthreads();

        float s_acc[4][4];
        #pragma unroll
        for (int i = 0; i < 4; i++)
            #pragma unroll
            for (int j = 0; j < 4; j++) s_acc[i][j] = 0.f;

        #pragma unroll 4
        for (int d = 0; d < 128; d++) {
            float a[4], bb[4];
            #pragma unroll
            for (int i = 0; i < 4; i++) a[i] = Qs[(ty*4 + i) * 129 + d];
            #pragma unroll
            for (int j = 0; j < 4; j++) bb[j] = Ks[(tx*4 + j) * 129 + d];
            #pragma unroll
            for (int i = 0; i < 4; i++)
                #pragma unroll
                for (int j = 0; j < 4; j++)
                    s_acc[i][j] = fmaf(a[i], bb[j], s_acc[i][j]);
        }

        if (kt == ntiles - 1) {
            #pragma unroll
            for (int i = 0; i < 4; i++)
                #pragma unroll
                for (int j = 0; j < 4; j++)
                    if (k0 + tx*4 + j > q0 + ty*4 + i) s_acc[i][j] = -1e30f;
        }

        #pragma unroll
        for (int i = 0; i < 4; i++) {
            float rm = fmaxf(fmaxf(s_acc[i][0], s_acc[i][1]),
                             fmaxf(s_acc[i][2], s_acc[i][3]));
            #pragma unroll
            for (int off = 8; off > 0; off >>= 1)
                rm = fmaxf(rm, __shfl_xor_sync(0xffffffffu, rm, off, 16));
            float mn = fmaxf(m_i[i], rm);
            float alpha = __expf(m_i[i] - mn);
            float psum = 0.f;
            #pragma unroll
            for (int j = 0; j < 4; j++) {
                float pp = __expf(s_acc[i][j] - mn);
                s_acc[i][j] = pp;
                psum += pp;
            }
            #pragma unroll
            for (int off = 8; off > 0; off >>= 1)
                psum += __shfl_xor_sync(0xffffffffu, psum, off, 16);
            l_i[i] = l_i[i] * alpha + psum;
            m_i[i] = mn;
            #pragma unroll
            for (int j = 0; j < 8; j++) acc[i][j] *= alpha;
            float* pr = &Ps[(ty*4 + i) * 65 + tx*4];
            pr[0] = s_acc[i][0]; pr[1] = s_acc[i][1];
            pr[2] = s_acc[i][2]; pr[3] = s_acc[i][3];
        }
        __syncthreads();

        #pragma unroll 2
        for (int k = 0; k < 64; k++) {
            float a[4];
            #pragma unroll
            for (int i = 0; i < 4; i++) a[i] = Ps[(ty*4 + i) * 65 + k];
            float4 vL = *(const float4*)&Vs[k * 128 + tx*4];
            float4 vH = *(const float4*)&Vs[k * 128 + 64 + tx*4];
            float vv[8] = {vL.x, vL.y, vL.z, vL.w, vH.x, vH.y, vH.z, vH.w};
            #pragma unroll
            for (int i = 0; i < 4; i++)
                #pragma unroll
                for (int j = 0; j < 8; j++)
                    acc[i][j] = fmaf(a[i], vv[j], acc[i][j]);
        }
    }

    // Epilogue: normalize + round to tf32 (feeds tf32 out-projection GEMM)
    #pragma unroll
    for (int i = 0; i < 4; i++) {
        float inv = 1.0f / l_i[i];
        size_t orow = ((size_t)(b * SEQ + q0 + ty*4 + i)) * D_MODEL + h * HEAD_DIM;
        float4 oL = make_float4(tf32r(acc[i][0]*inv), tf32r(acc[i][1]*inv),
                                tf32r(acc[i][2]*inv), tf32r(acc[i][3]*inv));
        float4 oH = make_float4(tf32r(acc[i][4]*inv), tf32r(acc[i][5]*inv),
                                tf32r(acc[i][6]*inv), tf32r(acc[i][7]*inv));
        *(float4*)(O + orow + tx*4)      = oL;
        *(float4*)(O + orow + 64 + tx*4) = oH;
    }
}

// ---------------------------------------------------------------------------
extern "C" void kernel_launch(void* const* d_in, const int* in_sizes, int n_in,
                              void* d_out, int out_size)
{
    const float* X  = (const float*)d_in[0];
    const float* Wq = (const float*)d_in[1];
    const float* Wk = (const float*)d_in[2];
    const float* Wv = (const float*)d_in[3];
    const float* Wo = (const float*)d_in[4];
    float* out = (float*)d_out;

    float *q, *k, *v, *o, *xt, *wt;
    cudaGetSymbolAddress((void**)&q, g_q);
    cudaGetSymbolAddress((void**)&k, g_k);
    cudaGetSymbolAddress((void**)&v, g_v);
    cudaGetSymbolAddress((void**)&o, g_o);
    cudaGetSymbolAddress((void**)&xt, g_xt);
    cudaGetSymbolAddress((void**)&wt, g_wt);
    float* wqt = wt;
    float* wkt = wt + (size_t)D_MODEL * D_MODEL;
    float* wvt = wt + 2 * (size_t)D_MODEL * D_MODEL;
    float* wot = wt + 3 * (size_t)D_MODEL * D_MODEL;

    cudaFuncSetAttribute(attn_kernel, cudaFuncAttributeMaxDynamicSharedMemorySize,
                         ATTN_SMEM_BYTES);
    cudaFuncSetAttribute(gemm_tf32, cudaFuncAttributeMaxDynamicSharedMemorySize,
                         GEMM_SMEM_BYTES);

    // 1) pre-round GEMM operands to tf32
    {
        int nx4 = (MROWS * D_MODEL) / 4;
        int nw4 = (D_MODEL * D_MODEL) / 4;
        tf32_round<<<(nx4 + 255) / 256, 256>>>((const float4*)X,  (float4*)xt,  nx4);
        tf32_round<<<(nw4 + 255) / 256, 256>>>((const float4*)Wq, (float4*)wqt, nw4);
        tf32_round<<<(nw4 + 255) / 256, 256>>>((const float4*)Wk, (float4*)wkt, nw4);
        tf32_round<<<(nw4 + 255) / 256, 256>>>((const float4*)Wv, (float4*)wvt, nw4);
        tf32_round<<<(nw4 + 255) / 256, 256>>>((const float4*)Wo, (float4*)wot, nw4);
    }

    dim3 gg(D_MODEL / BN, MROWS / BM);
    dim3 blk(256);

    // 2) QKV projections (tensor cores, tf32)
    gemm_tf32<<<gg, blk, GEMM_SMEM_BYTES>>>(xt, wqt, q, MROWS, D_MODEL, D_MODEL);
    gemm_tf32<<<gg, blk, GEMM_SMEM_BYTES>>>(xt, wkt, k, MROWS, D_MODEL, D_MODEL);
    gemm_tf32<<<gg, blk, GEMM_SMEM_BYTES>>>(xt, wvt, v, MROWS, D_MODEL, D_MODEL);

    // 3) RoPE
    rope_kernel<<<(MROWS * N_HEADS * 64) / 256, 256>>>(q, k);

    // 4) attention
    attn_kernel<<<dim3(SEQ / 64, BATCH * N_HEADS), 256, ATTN_SMEM_BYTES>>>(q, k, v, o);

    // 5) output projection
    gemm_tf32<<<gg, blk, GEMM_SMEM_BYTES>>>(o, wot, out, MROWS, D_MODEL, D_MODEL);
}

// round 4
// speedup vs baseline: 2.7861x; 1.5117x over previous
#include <cuda_runtime.h>
#include <math.h>
#include <stdint.h>

#define D_MODEL 2048
#define N_HEADS 16
#define HEAD_DIM 128
#define SEQ 2048
#define BATCH 2
#define MROWS (BATCH*SEQ)   // 4096

// Scratch (static device globals; no allocation allowed)
__device__ float g_q[(size_t)MROWS * D_MODEL];
__device__ float g_k[(size_t)MROWS * D_MODEL];
__device__ float g_v[(size_t)MROWS * D_MODEL];
__device__ float g_o[(size_t)MROWS * D_MODEL];
__device__ float g_xt[(size_t)MROWS * D_MODEL];          // tf32-rounded X
__device__ float g_wt[4][(size_t)D_MODEL * D_MODEL];     // tf32-rounded Wq,Wk,Wv,Wo

// ---------------------------------------------------------------------------
// helpers
// ---------------------------------------------------------------------------
__device__ __forceinline__ float tf32r(float x) {
    uint32_t u;
    asm("cvt.rna.tf32.f32 %0, %1;" : "=r"(u) : "f"(x));
    return __uint_as_float(u);
}

__global__ void tf32_round(const float4* __restrict__ src, float4* __restrict__ dst, int n4)
{
    int i = blockIdx.x * blockDim.x + threadIdx.x;
    if (i >= n4) return;
    float4 v = src[i];
    v.x = tf32r(v.x); v.y = tf32r(v.y); v.z = tf32r(v.z); v.w = tf32r(v.w);
    dst[i] = v;
}

__device__ __forceinline__ void cpa16(float* s, const float* g) {
    unsigned saddr = (unsigned)__cvta_generic_to_shared(s);
    asm volatile("cp.async.cg.shared.global [%0], [%1], 16;" :: "r"(saddr), "l"(g));
}

__device__ __forceinline__ void mma_tf32(float* c,
                                         uint32_t a0, uint32_t a1, uint32_t a2, uint32_t a3,
                                         uint32_t b0, uint32_t b1)
{
    asm volatile(
        "mma.sync.aligned.m16n8k8.row.col.f32.tf32.tf32.f32 "
        "{%0,%1,%2,%3},{%4,%5,%6,%7},{%8,%9},{%0,%1,%2,%3};"
        : "+f"(c[0]), "+f"(c[1]), "+f"(c[2]), "+f"(c[3])
        : "r"(a0), "r"(a1), "r"(a2), "r"(a3), "r"(b0), "r"(b1));
}

// ---------------------------------------------------------------------------
// tf32 tensor-core GEMM NT: C[M,N] = A[M,K] * B[N,K]^T
// ---------------------------------------------------------------------------
#define BM 128
#define BN 128
#define BK 32
#define LDS_STRIDE 36
#define GEMM_SMEM_BYTES (2 * (BM + BN) * LDS_STRIDE * 4)

__global__ __launch_bounds__(256) void gemm_tf32(const float* __restrict__ A,
                                                 const float* __restrict__ B,
                                                 float* __restrict__ C,
                                                 int M, int N, int K)
{
    extern __shared__ float sm[];
    float* As = sm;
    float* Bs = sm + 2 * BM * LDS_STRIDE;

    const int tid  = threadIdx.x;
    const int warp = tid >> 5;
    const int lane = tid & 31;
    const int wm = (warp >> 2) * 64;
    const int wn = (warp & 3) * 32;
    const int lr = lane >> 2;
    const int lc = lane & 3;

    const int m0 = blockIdx.y * BM;
    const int n0 = blockIdx.x * BN;

    const int ldr = tid >> 3;
    const int ldc = (tid & 7) * 4;

    float c[4][4][4];
    #pragma unroll
    for (int i = 0; i < 4; i++)
        #pragma unroll
        for (int j = 0; j < 4; j++)
            #pragma unroll
            for (int e = 0; e < 4; e++) c[i][j][e] = 0.f;

    const int nk = K / BK;

    {
        const float* Ag = A + (size_t)(m0 + ldr) * K + ldc;
        const float* Bg = B + (size_t)(n0 + ldr) * K + ldc;
        float* Asd = As + ldr * LDS_STRIDE + ldc;
        float* Bsd = Bs + ldr * LDS_STRIDE + ldc;
        #pragma unroll
        for (int i = 0; i < 4; i++) {
            cpa16(Asd + 32 * i * LDS_STRIDE, Ag + (size_t)(32 * i) * K);
            cpa16(Bsd + 32 * i * LDS_STRIDE, Bg + (size_t)(32 * i) * K);
        }
        asm volatile("cp.async.commit_group;");
    }

    for (int kt = 0; kt < nk; kt++) {
        asm volatile("cp.async.wait_group 0;");
        __syncthreads();

        if (kt + 1 < nk) {
            const int kb = (kt + 1) * BK;
            const int buf = (kt + 1) & 1;
            const float* Ag = A + (size_t)(m0 + ldr) * K + kb + ldc;
            const float* Bg = B + (size_t)(n0 + ldr) * K + kb + ldc;
            float* Asd = As + buf * BM * LDS_STRIDE + ldr * LDS_STRIDE + ldc;
            float* Bsd = Bs + buf * BN * LDS_STRIDE + ldr * LDS_STRIDE + ldc;
            #pragma unroll
            for (int i = 0; i < 4; i++) {
                cpa16(Asd + 32 * i * LDS_STRIDE, Ag + (size_t)(32 * i) * K);
                cpa16(Bsd + 32 * i * LDS_STRIDE, Bg + (size_t)(32 * i) * K);
            }
            asm volatile("cp.async.commit_group;");
        }

        const uint32_t* as_u = (const uint32_t*)(As + (kt & 1) * BM * LDS_STRIDE);
        const uint32_t* bs_u = (const uint32_t*)(Bs + (kt & 1) * BN * LDS_STRIDE);

        #pragma unroll
        for (int ks = 0; ks < 4; ks++) {
            const int kk = ks * 8;
            uint32_t a[4][4], b[4][2];
            #pragma unroll
            for (int mt = 0; mt < 4; mt++) {
                int base = (wm + mt * 16 + lr) * LDS_STRIDE + kk + lc;
                a[mt][0] = as_u[base];
                a[mt][1] = as_u[base + 8 * LDS_STRIDE];
                a[mt][2] = as_u[base + 4];
                a[mt][3] = as_u[base + 8 * LDS_STRIDE + 4];
            }
            #pragma unroll
            for (int nt = 0; nt < 4; nt++) {
                int base = (wn + nt * 8 + lr) * LDS_STRIDE + kk + lc;
                b[nt][0] = bs_u[base];
                b[nt][1] = bs_u[base + 4];
            }
            #pragma unroll
            for (int mt = 0; mt < 4; mt++)
                #pragma unroll
                for (int nt = 0; nt < 4; nt++)
                    mma_tf32(c[mt][nt], a[mt][0], a[mt][1], a[mt][2], a[mt][3],
                             b[nt][0], b[nt][1]);
        }
    }

    #pragma unroll
    for (int mt = 0; mt < 4; mt++) {
        #pragma unroll
        for (int nt = 0; nt < 4; nt++) {
            int row = m0 + wm + mt * 16 + lr;
            int col = n0 + wn + nt * 8 + 2 * lc;
            *(float2*)(C + (size_t)row * N + col)       = make_float2(c[mt][nt][0], c[mt][nt][1]);
            *(float2*)(C + (size_t)(row + 8) * N + col) = make_float2(c[mt][nt][2], c[mt][nt][3]);
        }
    }
}

// ---------------------------------------------------------------------------
// RoPE, in place on Q and K
// ---------------------------------------------------------------------------
__global__ void rope_kernel(float* __restrict__ Q, float* __restrict__ Kc)
{
    int idx = blockIdx.x * blockDim.x + threadIdx.x;
    if (idx >= MROWS * N_HEADS * 64) return;
    int j   = idx & 63;
    int h   = (idx >> 6) & (N_HEADS - 1);
    int row = idx >> 10;
    int s   = row & (SEQ - 1);

    float inv = exp2f(-(float)j * (13.287712379549449f / 64.0f));
    float ang = (float)s * inv;
    float sn, cs;
    sincosf(ang, &sn, &cs);

    size_t base = (size_t)row * D_MODEL + h * HEAD_DIM + j;
    float q1 = Q[base], q2 = Q[base + 64];
    Q[base]      = q1 * cs - q2 * sn;
    Q[base + 64] = q2 * cs + q1 * sn;
    float k1 = Kc[base], k2 = Kc[base + 64];
    Kc[base]      = k1 * cs - k2 * sn;
    Kc[base + 64] = k2 * cs + k1 * sn;
}

// ---------------------------------------------------------------------------
// Flash attention, tf32 tensor cores. 128 q-rows/block, 64-key tiles, 8 warps.
// Warp w owns q-rows [w*16, w*16+16): S-tile 16x64, O-tile 16x128.
// Strides: Qs/Ks 132, Vs 136 (PV b conflict-free), Ps 68.
// ---------------------------------------------------------------------------
#define AT_BM 128
#define AT_BK 64
#define QS_STR 132
#define KS_STR 132
#define VS_STR 136
#define PS_STR 68
#define ATTN_SMEM_BYTES ((AT_BM*QS_STR + AT_BK*KS_STR + AT_BK*VS_STR + AT_BM*PS_STR) * 4)

__global__ __launch_bounds__(256, 1) void attn_tf32(const float* __restrict__ Q,
                                                    const float* __restrict__ K,
                                                    const float* __restrict__ V,
                                                    float* __restrict__ O)
{
    extern __shared__ float sm[];
    float* Qs = sm;                              // 128 x 132
    float* Ks = Qs + AT_BM * QS_STR;             // 64 x 132
    float* Vs = Ks + AT_BK * KS_STR;             // 64 x 136
    float* Ps = Vs + AT_BK * VS_STR;             // 128 x 68

    const int tid  = threadIdx.x;
    const int warp = tid >> 5;
    const int lane = tid & 31;
    const int lr = lane >> 2;
    const int lc = lane & 3;
    const int wm = warp * 16;

    const int q0 = blockIdx.x * AT_BM;
    const int b  = blockIdx.y >> 4;
    const int h  = blockIdx.y & (N_HEADS - 1);
    const float scale = 0.088388347648318447f;  // 1/sqrt(128)

    const float* Qb = Q + ((size_t)(b * SEQ + q0)) * D_MODEL + h * HEAD_DIM;
    const float* Kb = K + ((size_t)(b * SEQ)) * D_MODEL + h * HEAD_DIM;
    const float* Vb = V + ((size_t)(b * SEQ)) * D_MODEL + h * HEAD_DIM;

    // Load Q tile: scale + round to tf32
    for (int p = tid; p < AT_BM * 32; p += 256) {
        int r = p >> 5, d4 = (p & 31) << 2;
        float4 v = *(const float4*)(Qb + (size_t)r * D_MODEL + d4);
        float* dst = &Qs[r * QS_STR + d4];
        dst[0] = tf32r(v.x * scale); dst[1] = tf32r(v.y * scale);
        dst[2] = tf32r(v.z * scale); dst[3] = tf32r(v.w * scale);
    }

    float o_acc[16][4];
    #pragma unroll
    for (int i = 0; i < 16; i++)
        #pragma unroll
        for (int e = 0; e < 4; e++) o_acc[i][e] = 0.f;
    float m0 = -1e30f, m1 = -1e30f, l0 = 0.f, l1 = 0.f;

    const uint32_t* qs_u = (const uint32_t*)Qs;
    const uint32_t* ks_u = (const uint32_t*)Ks;
    const uint32_t* vs_u = (const uint32_t*)Vs;
    const uint32_t* ps_u = (const uint32_t*)Ps;

    const int r0g = q0 + wm + lr;
    const int r1g = r0g + 8;

    const int ntiles = 2 * blockIdx.x + 2;
    for (int kt = 0; kt < ntiles; kt++) {
        const int k0 = kt * AT_BK;
        __syncthreads();
        for (int p = tid; p < AT_BK * 32; p += 256) {
            int r = p >> 5, d4 = (p & 31) << 2;
            float4 kv = *(const float4*)(Kb + (size_t)(k0 + r) * D_MODEL + d4);
            float* kd = &Ks[r * KS_STR + d4];
            kd[0] = tf32r(kv.x); kd[1] = tf32r(kv.y);
            kd[2] = tf32r(kv.z); kd[3] = tf32r(kv.w);
            float4 vv = *(const float4*)(Vb + (size_t)(k0 + r) * D_MODEL + d4);
            float* vd = &Vs[r * VS_STR + d4];
            vd[0] = tf32r(vv.x); vd[1] = tf32r(vv.y);
            vd[2] = tf32r(vv.z); vd[3] = tf32r(vv.w);
        }
        __syncthreads();

        // S = Q @ K^T  (16x64 per warp)
        float s[8][4];
        #pragma unroll
        for (int nt = 0; nt < 8; nt++)
            #pragma unroll
            for (int e = 0; e < 4; e++) s[nt][e] = 0.f;

        #pragma unroll
        for (int ks = 0; ks < 16; ks++) {
            const int kk = ks * 8;
            int ab = (wm + lr) * QS_STR + kk + lc;
            uint32_t a0 = qs_u[ab];
            uint32_t a1 = qs_u[ab + 8 * QS_STR];
            uint32_t a2 = qs_u[ab + 4];
            uint32_t a3 = qs_u[ab + 8 * QS_STR + 4];
            #pragma unroll
            for (int nt = 0; nt < 8; nt++) {
                int bb = (nt * 8 + lr) * KS_STR + kk + lc;
                mma_tf32(s[nt], a0, a1, a2, a3, ks_u[bb], ks_u[bb + 4]);
            }
        }

        // mask + online softmax
        float rm0 = -1e30f, rm1 = -1e30f;
        #pragma unroll
        for (int nt = 0; nt < 8; nt++) {
            int c0 = k0 + nt * 8 + 2 * lc;
            if (c0     > r0g) s[nt][0] = -1e30f;
            if (c0 + 1 > r0g) s[nt][1] = -1e30f;
            if (c0     > r1g) s[nt][2] = -1e30f;
            if (c0 + 1 > r1g) s[nt][3] = -1e30f;
            rm0 = fmaxf(rm0, fmaxf(s[nt][0], s[nt][1]));
            rm1 = fmaxf(rm1, fmaxf(s[nt][2], s[nt][3]));
        }
        rm0 = fmaxf(rm0, __shfl_xor_sync(0xffffffffu, rm0, 1));
        rm0 = fmaxf(rm0, __shfl_xor_sync(0xffffffffu, rm0, 2));
        rm1 = fmaxf(rm1, __shfl_xor_sync(0xffffffffu, rm1, 1));
        rm1 = fmaxf(rm1, __shfl_xor_sync(0xffffffffu, rm1, 2));

        float mn0 = fmaxf(m0, rm0), mn1 = fmaxf(m1, rm1);
        float al0 = __expf(m0 - mn0), al1 = __expf(m1 - mn1);
        m0 = mn0; m1 = mn1;

        float ps0 = 0.f, ps1 = 0.f;
        #pragma unroll
        for (int nt = 0; nt < 8; nt++) {
            float p00 = __expf(s[nt][0] - mn0);
            float p01 = __expf(s[nt][1] - mn0);
            float p10 = __expf(s[nt][2] - mn1);
            float p11 = __expf(s[nt][3] - mn1);
            ps0 += p00 + p01;
            ps1 += p10 + p11;
            int pb = (wm + lr) * PS_STR + nt * 8 + 2 * lc;
            Ps[pb]     = tf32r(p00);
            Ps[pb + 1] = tf32r(p01);
            Ps[pb + 8 * PS_STR]     = tf32r(p10);
            Ps[pb + 8 * PS_STR + 1] = tf32r(p11);
        }
        ps0 += __shfl_xor_sync(0xffffffffu, ps0, 1);
        ps0 += __shfl_xor_sync(0xffffffffu, ps0, 2);
        ps1 += __shfl_xor_sync(0xffffffffu, ps1, 1);
        ps1 += __shfl_xor_sync(0xffffffffu, ps1, 2);
        l0 = l0 * al0 + ps0;
        l1 = l1 * al1 + ps1;

        #pragma unroll
        for (int nt2 = 0; nt2 < 16; nt2++) {
            o_acc[nt2][0] *= al0; o_acc[nt2][1] *= al0;
            o_acc[nt2][2] *= al1; o_acc[nt2][3] *= al1;
        }
        __syncwarp();

        // O += P @ V   (16x128 per warp; P rows are warp-local)
        #pragma unroll
        for (int ks = 0; ks < 8; ks++) {
            const int kk = ks * 8;
            int ab = (wm + lr) * PS_STR + kk + lc;
            uint32_t a0 = ps_u[ab];
            uint32_t a1 = ps_u[ab + 8 * PS_STR];
            uint32_t a2 = ps_u[ab + 4];
            uint32_t a3 = ps_u[ab + 8 * PS_STR + 4];
            #pragma unroll
            for (int nt2 = 0; nt2 < 16; nt2++) {
                int vb = (kk + lc) * VS_STR + nt2 * 8 + lr;
                mma_tf32(o_acc[nt2], a0, a1, a2, a3, vs_u[vb], vs_u[vb + 4 * VS_STR]);
            }
        }
        __syncwarp();
    }

    // epilogue: normalize, round to tf32 (feeds out-projection), store
    float inv0 = 1.0f / l0, inv1 = 1.0f / l1;
    float* Ob = O + ((size_t)(b * SEQ + q0 + wm + lr)) * D_MODEL + h * HEAD_DIM;
    #pragma unroll
    for (int nt2 = 0; nt2 < 16; nt2++) {
        int col = nt2 * 8 + 2 * lc;
        *(float2*)(Ob + col) = make_float2(tf32r(o_acc[nt2][0] * inv0),
                                           tf32r(o_acc[nt2][1] * inv0));
        *(float2*)(Ob + 8 * D_MODEL + col) = make_float2(tf32r(o_acc[nt2][2] * inv1),
                                                         tf32r(o_acc[nt2][3] * inv1));
    }
}

// ---------------------------------------------------------------------------
extern "C" void kernel_launch(void* const* d_in, const int* in_sizes, int n_in,
                              void* d_out, int out_size)
{
    const float* X  = (const float*)d_in[0];
    const float* Wq = (const float*)d_in[1];
    const float* Wk = (const float*)d_in[2];
    const float* Wv = (const float*)d_in[3];
    const float* Wo = (const float*)d_in[4];
    float* out = (float*)d_out;

    float *q, *k, *v, *o, *xt, *wt;
    cudaGetSymbolAddress((void**)&q, g_q);
    cudaGetSymbolAddress((void**)&k, g_k);
    cudaGetSymbolAddress((void**)&v, g_v);
    cudaGetSymbolAddress((void**)&o, g_o);
    cudaGetSymbolAddress((void**)&xt, g_xt);
    cudaGetSymbolAddress((void**)&wt, g_wt);
    float* wqt = wt;
    float* wkt = wt + (size_t)D_MODEL * D_MODEL;
    float* wvt = wt + 2 * (size_t)D_MODEL * D_MODEL;
    float* wot = wt + 3 * (size_t)D_MODEL * D_MODEL;

    cudaFuncSetAttribute(attn_tf32, cudaFuncAttributeMaxDynamicSharedMemorySize,
                         ATTN_SMEM_BYTES);
    cudaFuncSetAttribute(gemm_tf32, cudaFuncAttributeMaxDynamicSharedMemorySize,
                         GEMM_SMEM_BYTES);

    // 1) pre-round GEMM operands to tf32
    {
        int nx4 = (MROWS * D_MODEL) / 4;
        int nw4 = (D_MODEL * D_MODEL) / 4;
        tf32_round<<<(nx4 + 255) / 256, 256>>>((const float4*)X,  (float4*)xt,  nx4);
        tf32_round<<<(nw4 + 255) / 256, 256>>>((const float4*)Wq, (float4*)wqt, nw4);
        tf32_round<<<(nw4 + 255) / 256, 256>>>((const float4*)Wk, (float4*)wkt, nw4);
        tf32_round<<<(nw4 + 255) / 256, 256>>>((const float4*)Wv, (float4*)wvt, nw4);
        tf32_round<<<(nw4 + 255) / 256, 256>>>((const float4*)Wo, (float4*)wot, nw4);
    }

    dim3 gg(D_MODEL / BN, MROWS / BM);
    dim3 blk(256);

    // 2) QKV projections
    gemm_tf32<<<gg, blk, GEMM_SMEM_BYTES>>>(xt, wqt, q, MROWS, D_MODEL, D_MODEL);
    gemm_tf32<<<gg, blk, GEMM_SMEM_BYTES>>>(xt, wkt, k, MROWS, D_MODEL, D_MODEL);
    gemm_tf32<<<gg, blk, GEMM_SMEM_BYTES>>>(xt, wvt, v, MROWS, D_MODEL, D_MODEL);

    // 3) RoPE
    rope_kernel<<<(MROWS * N_HEADS * 64) / 256, 256>>>(q, k);

    // 4) attention (tensor cores)
    attn_tf32<<<dim3(SEQ / AT_BM, BATCH * N_HEADS), 256, ATTN_SMEM_BYTES>>>(q, k, v, o);

    // 5) output projection
    gemm_tf32<<<gg, blk, GEMM_SMEM_BYTES>>>(o, wot, out, MROWS, D_MODEL, D_MODEL);
}

// round 5
// speedup vs baseline: 3.4064x; 1.2226x over previous
#include <cuda_runtime.h>
#include <math.h>
#include <stdint.h>

#define D_MODEL 2048
#define N_HEADS 16
#define HEAD_DIM 128
#define SEQ 2048
#define BATCH 2
#define MROWS (BATCH*SEQ)   // 4096

// Scratch (static device globals; no allocation allowed)
__device__ float g_q[(size_t)MROWS * D_MODEL];
__device__ float g_k[(size_t)MROWS * D_MODEL];
__device__ float g_v[(size_t)MROWS * D_MODEL];
__device__ float g_o[(size_t)MROWS * D_MODEL];
__device__ float g_xt[(size_t)MROWS * D_MODEL];          // tf32-rounded X
__device__ float g_wt[4][(size_t)D_MODEL * D_MODEL];     // tf32-rounded Wq,Wk,Wv,Wo

// ---------------------------------------------------------------------------
// helpers
// ---------------------------------------------------------------------------
__device__ __forceinline__ float tf32r(float x) {
    uint32_t u;
    asm("cvt.rna.tf32.f32 %0, %1;" : "=r"(u) : "f"(x));
    return __uint_as_float(u);
}

__global__ void tf32_round(const float4* __restrict__ src, float4* __restrict__ dst, int n4)
{
    int i = blockIdx.x * blockDim.x + threadIdx.x;
    if (i >= n4) return;
    float4 v = src[i];
    v.x = tf32r(v.x); v.y = tf32r(v.y); v.z = tf32r(v.z); v.w = tf32r(v.w);
    dst[i] = v;
}

__device__ __forceinline__ void cpa16(float* s, const float* g) {
    unsigned saddr = (unsigned)__cvta_generic_to_shared(s);
    asm volatile("cp.async.cg.shared.global [%0], [%1], 16;" :: "r"(saddr), "l"(g));
}

__device__ __forceinline__ void mma_tf32(float* c,
                                         uint32_t a0, uint32_t a1, uint32_t a2, uint32_t a3,
                                         uint32_t b0, uint32_t b1)
{
    asm volatile(
        "mma.sync.aligned.m16n8k8.row.col.f32.tf32.tf32.f32 "
        "{%0,%1,%2,%3},{%4,%5,%6,%7},{%8,%9},{%0,%1,%2,%3};"
        : "+f"(c[0]), "+f"(c[1]), "+f"(c[2]), "+f"(c[3])
        : "r"(a0), "r"(a1), "r"(a2), "r"(a3), "r"(b0), "r"(b1));
}

// ---------------------------------------------------------------------------
// tf32 tensor-core GEMM NT: C[M,N] = A[M,K] * B[N,K]^T
// Block 128x128, 4 warps (128 thr), warp tile 64x64, BK=32, 2-stage cp.async.
// 2 CTAs/SM (smem 73.7KB, ~190 regs/thread).
// ---------------------------------------------------------------------------
#define BM 128
#define BN 128
#define BK 32
#define LDS_STRIDE 36
#define GEMM_SMEM_BYTES (2 * (BM + BN) * LDS_STRIDE * 4)

__global__ __launch_bounds__(128, 2) void gemm_tf32(const float* __restrict__ A,
                                                    const float* __restrict__ B,
                                                    float* __restrict__ C,
                                                    int M, int N, int K)
{
    extern __shared__ float sm[];
    float* As = sm;                          // 2 x [128][36]
    float* Bs = sm + 2 * BM * LDS_STRIDE;    // 2 x [128][36]

    const int tid  = threadIdx.x;
    const int warp = tid >> 5;
    const int lane = tid & 31;
    const int wm = (warp >> 1) * 64;   // 0,64
    const int wn = (warp & 1) * 64;    // 0,64
    const int lr = lane >> 2;          // 0..7
    const int lc = lane & 3;           // 0..3

    const int m0 = blockIdx.y * BM;
    const int n0 = blockIdx.x * BN;

    // loader: 128 threads, 8 float4 each per tile (rows tid/8 + 16i, col (tid%8)*4)
    const int ldr = tid >> 3;          // 0..15
    const int ldc = (tid & 7) * 4;     // 0,4,..,28

    float c[4][8][4];
    #pragma unroll
    for (int i = 0; i < 4; i++)
        #pragma unroll
        for (int j = 0; j < 8; j++)
            #pragma unroll
            for (int e = 0; e < 4; e++) c[i][j][e] = 0.f;

    const int nk = K / BK;

    // prologue: tile 0 -> buffer 0
    {
        const float* Ag = A + (size_t)(m0 + ldr) * K + ldc;
        const float* Bg = B + (size_t)(n0 + ldr) * K + ldc;
        float* Asd = As + ldr * LDS_STRIDE + ldc;
        float* Bsd = Bs + ldr * LDS_STRIDE + ldc;
        #pragma unroll
        for (int i = 0; i < 8; i++) {
            cpa16(Asd + 16 * i * LDS_STRIDE, Ag + (size_t)(16 * i) * K);
            cpa16(Bsd + 16 * i * LDS_STRIDE, Bg + (size_t)(16 * i) * K);
        }
        asm volatile("cp.async.commit_group;");
    }

    for (int kt = 0; kt < nk; kt++) {
        asm volatile("cp.async.wait_group 0;");
        __syncthreads();

        if (kt + 1 < nk) {
            const int kb = (kt + 1) * BK;
            const int buf = (kt + 1) & 1;
            const float* Ag = A + (size_t)(m0 + ldr) * K + kb + ldc;
            const float* Bg = B + (size_t)(n0 + ldr) * K + kb + ldc;
            float* Asd = As + buf * BM * LDS_STRIDE + ldr * LDS_STRIDE + ldc;
            float* Bsd = Bs + buf * BN * LDS_STRIDE + ldr * LDS_STRIDE + ldc;
            #pragma unroll
            for (int i = 0; i < 8; i++) {
                cpa16(Asd + 16 * i * LDS_STRIDE, Ag + (size_t)(16 * i) * K);
                cpa16(Bsd + 16 * i * LDS_STRIDE, Bg + (size_t)(16 * i) * K);
            }
            asm volatile("cp.async.commit_group;");
        }

        const uint32_t* as_u = (const uint32_t*)(As + (kt & 1) * BM * LDS_STRIDE);
        const uint32_t* bs_u = (const uint32_t*)(Bs + (kt & 1) * BN * LDS_STRIDE);

        #pragma unroll
        for (int ks = 0; ks < 4; ks++) {
            const int kk = ks * 8;
            uint32_t a[4][4], b[8][2];
            #pragma unroll
            for (int mt = 0; mt < 4; mt++) {
                int base = (wm + mt * 16 + lr) * LDS_STRIDE + kk + lc;
                a[mt][0] = as_u[base];
                a[mt][1] = as_u[base + 8 * LDS_STRIDE];
                a[mt][2] = as_u[base + 4];
                a[mt][3] = as_u[base + 8 * LDS_STRIDE + 4];
            }
            #pragma unroll
            for (int nt = 0; nt < 8; nt++) {
                int base = (wn + nt * 8 + lr) * LDS_STRIDE + kk + lc;
                b[nt][0] = bs_u[base];
                b[nt][1] = bs_u[base + 4];
            }
            #pragma unroll
            for (int mt = 0; mt < 4; mt++)
                #pragma unroll
                for (int nt = 0; nt < 8; nt++)
                    mma_tf32(c[mt][nt], a[mt][0], a[mt][1], a[mt][2], a[mt][3],
                             b[nt][0], b[nt][1]);
        }
    }

    // epilogue
    #pragma unroll
    for (int mt = 0; mt < 4; mt++) {
        #pragma unroll
        for (int nt = 0; nt < 8; nt++) {
            int row = m0 + wm + mt * 16 + lr;
            int col = n0 + wn + nt * 8 + 2 * lc;
            *(float2*)(C + (size_t)row * N + col)       = make_float2(c[mt][nt][0], c[mt][nt][1]);
            *(float2*)(C + (size_t)(row + 8) * N + col) = make_float2(c[mt][nt][2], c[mt][nt][3]);
        }
    }
}

// ---------------------------------------------------------------------------
// RoPE, in place on Q and K
// ---------------------------------------------------------------------------
__global__ void rope_kernel(float* __restrict__ Q, float* __restrict__ Kc)
{
    int idx = blockIdx.x * blockDim.x + threadIdx.x;
    if (idx >= MROWS * N_HEADS * 64) return;
    int j   = idx & 63;
    int h   = (idx >> 6) & (N_HEADS - 1);
    int row = idx >> 10;
    int s   = row & (SEQ - 1);

    float inv = exp2f(-(float)j * (13.287712379549449f / 64.0f));
    float ang = (float)s * inv;
    float sn, cs;
    sincosf(ang, &sn, &cs);

    size_t base = (size_t)row * D_MODEL + h * HEAD_DIM + j;
    float q1 = Q[base], q2 = Q[base + 64];
    Q[base]      = q1 * cs - q2 * sn;
    Q[base + 64] = q2 * cs + q1 * sn;
    float k1 = Kc[base], k2 = Kc[base + 64];
    Kc[base]      = k1 * cs - k2 * sn;
    Kc[base + 64] = k2 * cs + k1 * sn;
}

// ---------------------------------------------------------------------------
// Flash attention, tf32 tensor cores. 128 q-rows/block, 64-key tiles, 8 warps.
// ---------------------------------------------------------------------------
#define AT_BM 128
#define AT_BK 64
#define QS_STR 132
#define KS_STR 132
#define VS_STR 136
#define PS_STR 68
#define ATTN_SMEM_BYTES ((AT_BM*QS_STR + AT_BK*KS_STR + AT_BK*VS_STR + AT_BM*PS_STR) * 4)

__global__ __launch_bounds__(256, 1) void attn_tf32(const float* __restrict__ Q,
                                                    const float* __restrict__ K,
                                                    const float* __restrict__ V,
                                                    float* __restrict__ O)
{
    extern __shared__ float sm[];
    float* Qs = sm;                              // 128 x 132
    float* Ks = Qs + AT_BM * QS_STR;             // 64 x 132
    float* Vs = Ks + AT_BK * KS_STR;             // 64 x 136
    float* Ps = Vs + AT_BK * VS_STR;             // 128 x 68

    const int tid  = threadIdx.x;
    const int warp = tid >> 5;
    const int lane = tid & 31;
    const int lr = lane >> 2;
    const int lc = lane & 3;
    const int wm = warp * 16;

    const int q0 = blockIdx.x * AT_BM;
    const int b  = blockIdx.y >> 4;
    const int h  = blockIdx.y & (N_HEADS - 1);
    const float scale = 0.088388347648318447f;  // 1/sqrt(128)

    const float* Qb = Q + ((size_t)(b * SEQ + q0)) * D_MODEL + h * HEAD_DIM;
    const float* Kb = K + ((size_t)(b * SEQ)) * D_MODEL + h * HEAD_DIM;
    const float* Vb = V + ((size_t)(b * SEQ)) * D_MODEL + h * HEAD_DIM;

    for (int p = tid; p < AT_BM * 32; p += 256) {
        int r = p >> 5, d4 = (p & 31) << 2;
        float4 v = *(const float4*)(Qb + (size_t)r * D_MODEL + d4);
        float* dst = &Qs[r * QS_STR + d4];
        dst[0] = tf32r(v.x * scale); dst[1] = tf32r(v.y * scale);
        dst[2] = tf32r(v.z * scale); dst[3] = tf32r(v.w * scale);
    }

    float o_acc[16][4];
    #pragma unroll
    for (int i = 0; i < 16; i++)
        #pragma unroll
        for (int e = 0; e < 4; e++) o_acc[i][e] = 0.f;
    float m0 = -1e30f, m1 = -1e30f, l0 = 0.f, l1 = 0.f;

    const uint32_t* qs_u = (const uint32_t*)Qs;
    const uint32_t* ks_u = (const uint32_t*)Ks;
    const uint32_t* vs_u = (const uint32_t*)Vs;
    const uint32_t* ps_u = (const uint32_t*)Ps;

    const int r0g = q0 + wm + lr;
    const int r1g = r0g + 8;

    const int ntiles = 2 * blockIdx.x + 2;
    for (int kt = 0; kt < ntiles; kt++) {
        const int k0 = kt * AT_BK;
        __syncthreads();
        for (int p = tid; p < AT_BK * 32; p += 256) {
            int r = p >> 5, d4 = (p & 31) << 2;
            float4 kv = *(const float4*)(Kb + (size_t)(k0 + r) * D_MODEL + d4);
            float* kd = &Ks[r * KS_STR + d4];
            kd[0] = tf32r(kv.x); kd[1] = tf32r(kv.y);
            kd[2] = tf32r(kv.z); kd[3] = tf32r(kv.w);
            float4 vv = *(const float4*)(Vb + (size_t)(k0 + r) * D_MODEL + d4);
            float* vd = &Vs[r * VS_STR + d4];
            vd[0] = tf32r(vv.x); vd[1] = tf32r(vv.y);
            vd[2] = tf32r(vv.z); vd[3] = tf32r(vv.w);
        }
        __syncthreads();

        float s[8][4];
        #pragma unroll
        for (int nt = 0; nt < 8; nt++)
            #pragma unroll
            for (int e = 0; e < 4; e++) s[nt][e] = 0.f;

        #pragma unroll
        for (int ks = 0; ks < 16; ks++) {
            const int kk = ks * 8;
            int ab = (wm + lr) * QS_STR + kk + lc;
            uint32_t a0 = qs_u[ab];
            uint32_t a1 = qs_u[ab + 8 * QS_STR];
            uint32_t a2 = qs_u[ab + 4];
            uint32_t a3 = qs_u[ab + 8 * QS_STR + 4];
            #pragma unroll
            for (int nt = 0; nt < 8; nt++) {
                int bb = (nt * 8 + lr) * KS_STR + kk + lc;
                mma_tf32(s[nt], a0, a1, a2, a3, ks_u[bb], ks_u[bb + 4]);
            }
        }

        float rm0 = -1e30f, rm1 = -1e30f;
        #pragma unroll
        for (int nt = 0; nt < 8; nt++) {
            int c0 = k0 + nt * 8 + 2 * lc;
            if (c0     > r0g) s[nt][0] = -1e30f;
            if (c0 + 1 > r0g) s[nt][1] = -1e30f;
            if (c0     > r1g) s[nt][2] = -1e30f;
            if (c0 + 1 > r1g) s[nt][3] = -1e30f;
            rm0 = fmaxf(rm0, fmaxf(s[nt][0], s[nt][1]));
            rm1 = fmaxf(rm1, fmaxf(s[nt][2], s[nt][3]));
        }
        rm0 = fmaxf(rm0, __shfl_xor_sync(0xffffffffu, rm0, 1));
        rm0 = fmaxf(rm0, __shfl_xor_sync(0xffffffffu, rm0, 2));
        rm1 = fmaxf(rm1, __shfl_xor_sync(0xffffffffu, rm1, 1));
        rm1 = fmaxf(rm1, __shfl_xor_sync(0xffffffffu, rm1, 2));

        float mn0 = fmaxf(m0, rm0), mn1 = fmaxf(m1, rm1);
        float al0 = __expf(m0 - mn0), al1 = __expf(m1 - mn1);
        m0 = mn0; m1 = mn1;

        float ps0 = 0.f, ps1 = 0.f;
        #pragma unroll
        for (int nt = 0; nt < 8; nt++) {
            float p00 = __expf(s[nt][0] - mn0);
            float p01 = __expf(s[nt][1] - mn0);
            float p10 = __expf(s[nt][2] - mn1);
            float p11 = __expf(s[nt][3] - mn1);
            ps0 += p00 + p01;
            ps1 += p10 + p11;
            int pb = (wm + lr) * PS_STR + nt * 8 + 2 * lc;
            Ps[pb]     = tf32r(p00);
            Ps[pb + 1] = tf32r(p01);
            Ps[pb + 8 * PS_STR]     = tf32r(p10);
            Ps[pb + 8 * PS_STR + 1] = tf32r(p11);
        }
        ps0 += __shfl_xor_sync(0xffffffffu, ps0, 1);
        ps0 += __shfl_xor_sync(0xffffffffu, ps0, 2);
        ps1 += __shfl_xor_sync(0xffffffffu, ps1, 1);
        ps1 += __shfl_xor_sync(0xffffffffu, ps1, 2);
        l0 = l0 * al0 + ps0;
        l1 = l1 * al1 + ps1;

        #pragma unroll
        for (int nt2 = 0; nt2 < 16; nt2++) {
            o_acc[nt2][0] *= al0; o_acc[nt2][1] *= al0;
            o_acc[nt2][2] *= al1; o_acc[nt2][3] *= al1;
        }
        __syncwarp();

        #pragma unroll
        for (int ks = 0; ks < 8; ks++) {
            const int kk = ks * 8;
            int ab = (wm + lr) * PS_STR + kk + lc;
            uint32_t a0 = ps_u[ab];
            uint32_t a1 = ps_u[ab + 8 * PS_STR];
            uint32_t a2 = ps_u[ab + 4];
            uint32_t a3 = ps_u[ab + 8 * PS_STR + 4];
            #pragma unroll
            for (int nt2 = 0; nt2 < 16; nt2++) {
                int vb = (kk + lc) * VS_STR + nt2 * 8 + lr;
                mma_tf32(o_acc[nt2], a0, a1, a2, a3, vs_u[vb], vs_u[vb + 4 * VS_STR]);
            }
        }
        __syncwarp();
    }

    float inv0 = 1.0f / l0, inv1 = 1.0f / l1;
    float* Ob = O + ((size_t)(b * SEQ + q0 + wm + lr)) * D_MODEL + h * HEAD_DIM;
    #pragma unroll
    for (int nt2 = 0; nt2 < 16; nt2++) {
        int col = nt2 * 8 + 2 * lc;
        *(float2*)(Ob + col) = make_float2(tf32r(o_acc[nt2][0] * inv0),
                                           tf32r(o_acc[nt2][1] * inv0));
        *(float2*)(Ob + 8 * D_MODEL + col) = make_float2(tf32r(o_acc[nt2][2] * inv1),
                                                         tf32r(o_acc[nt2][3] * inv1));
    }
}

// ---------------------------------------------------------------------------
extern "C" void kernel_launch(void* const* d_in, const int* in_sizes, int n_in,
                              void* d_out, int out_size)
{
    const float* X  = (const float*)d_in[0];
    const float* Wq = (const float*)d_in[1];
    const float* Wk = (const float*)d_in[2];
    const float* Wv = (const float*)d_in[3];
    const float* Wo = (const float*)d_in[4];
    float* out = (float*)d_out;

    float *q, *k, *v, *o, *xt, *wt;
    cudaGetSymbolAddress((void**)&q, g_q);
    cudaGetSymbolAddress((void**)&k, g_k);
    cudaGetSymbolAddress((void**)&v, g_v);
    cudaGetSymbolAddress((void**)&o, g_o);
    cudaGetSymbolAddress((void**)&xt, g_xt);
    cudaGetSymbolAddress((void**)&wt, g_wt);
    float* wqt = wt;
    float* wkt = wt + (size_t)D_MODEL * D_MODEL;
    float* wvt = wt + 2 * (size_t)D_MODEL * D_MODEL;
    float* wot = wt + 3 * (size_t)D_MODEL * D_MODEL;

    cudaFuncSetAttribute(attn_tf32, cudaFuncAttributeMaxDynamicSharedMemorySize,
                         ATTN_SMEM_BYTES);
    cudaFuncSetAttribute(gemm_tf32, cudaFuncAttributeMaxDynamicSharedMemorySize,
                         GEMM_SMEM_BYTES);

    // 1) pre-round GEMM operands to tf32
    {
        int nx4 = (MROWS * D_MODEL) / 4;
        int nw4 = (D_MODEL * D_MODEL) / 4;
        tf32_round<<<(nx4 + 255) / 256, 256>>>((const float4*)X,  (float4*)xt,  nx4);
        tf32_round<<<(nw4 + 255) / 256, 256>>>((const float4*)Wq, (float4*)wqt, nw4);
        tf32_round<<<(nw4 + 255) / 256, 256>>>((const float4*)Wk, (float4*)wkt, nw4);
        tf32_round<<<(nw4 + 255) / 256, 256>>>((const float4*)Wv, (float4*)wvt, nw4);
        tf32_round<<<(nw4 + 255) / 256, 256>>>((const float4*)Wo, (float4*)wot, nw4);
    }

    dim3 gg(D_MODEL / BN, MROWS / BM);
    dim3 blk(128);

    // 2) QKV projections
    gemm_tf32<<<gg, blk, GEMM_SMEM_BYTES>>>(xt, wqt, q, MROWS, D_MODEL, D_MODEL);
    gemm_tf32<<<gg, blk, GEMM_SMEM_BYTES>>>(xt, wkt, k, MROWS, D_MODEL, D_MODEL);
    gemm_tf32<<<gg, blk, GEMM_SMEM_BYTES>>>(xt, wvt, v, MROWS, D_MODEL, D_MODEL);

    // 3) RoPE
    rope_kernel<<<(MROWS * N_HEADS * 64) / 256, 256>>>(q, k);

    // 4) attention (tensor cores)
    attn_tf32<<<dim3(SEQ / AT_BM, BATCH * N_HEADS), 256, ATTN_SMEM_BYTES>>>(q, k, v, o);

    // 5) output projection
    gemm_tf32<<<gg, blk, GEMM_SMEM_BYTES>>>(o, wot, out, MROWS, D_MODEL, D_MODEL);
}

// round 7
// speedup vs baseline: 5.0380x; 1.4790x over previous
#include <cuda_runtime.h>
#include <cuda_fp16.h>
#include <math.h>
#include <stdint.h>

#define D_MODEL 2048
#define N_HEADS 16
#define HEAD_DIM 128
#define SEQ 2048
#define BATCH 2
#define MROWS (BATCH*SEQ)   // 4096

// Scratch (static device globals; no allocation allowed)
__device__ float  g_q[(size_t)MROWS * D_MODEL];
__device__ float  g_k[(size_t)MROWS * D_MODEL];
__device__ float  g_v[(size_t)MROWS * D_MODEL];
__device__ __half g_xh[(size_t)MROWS * D_MODEL];          // fp16 X
__device__ __half g_oh[(size_t)MROWS * D_MODEL];          // fp16 attention output
__device__ __half g_wh[4][(size_t)D_MODEL * D_MODEL];     // fp16 Wq,Wk,Wv,Wo

// ---------------------------------------------------------------------------
// helpers
// ---------------------------------------------------------------------------
__device__ __forceinline__ float tf32r(float x) {
    uint32_t u;
    asm("cvt.rna.tf32.f32 %0, %1;" : "=r"(u) : "f"(x));
    return __uint_as_float(u);
}

__global__ void f2h(const float4* __restrict__ src, uint2* __restrict__ dst, int n4)
{
    int i = blockIdx.x * blockDim.x + threadIdx.x;
    if (i >= n4) return;
    float4 v = src[i];
    __half2 h01 = __floats2half2_rn(v.x, v.y);
    __half2 h23 = __floats2half2_rn(v.z, v.w);
    dst[i] = make_uint2(*(uint32_t*)&h01, *(uint32_t*)&h23);
}

__device__ __forceinline__ void cpa16s(uint32_t saddr, const void* g) {
    asm volatile("cp.async.cg.shared.global [%0], [%1], 16;" :: "r"(saddr), "l"(g));
}

__device__ __forceinline__ uint32_t s2u(const void* p) {
    uint32_t a;
    asm("{ .reg .u64 t; cvta.to.shared.u64 t, %1; cvt.u32.u64 %0, t; }" : "=r"(a) : "l"(p));
    return a;
}

__device__ __forceinline__ void mma_tf32(float* c,
                                         uint32_t a0, uint32_t a1, uint32_t a2, uint32_t a3,
                                         uint32_t b0, uint32_t b1)
{
    asm volatile(
        "mma.sync.aligned.m16n8k8.row.col.f32.tf32.tf32.f32 "
        "{%0,%1,%2,%3},{%4,%5,%6,%7},{%8,%9},{%0,%1,%2,%3};"
        : "+f"(c[0]), "+f"(c[1]), "+f"(c[2]), "+f"(c[3])
        : "r"(a0), "r"(a1), "r"(a2), "r"(a3), "r"(b0), "r"(b1));
}

__device__ __forceinline__ void mma_f16(float* c,
                                        uint32_t a0, uint32_t a1, uint32_t a2, uint32_t a3,
                                        uint32_t b0, uint32_t b1)
{
    asm volatile(
        "mma.sync.aligned.m16n8k16.row.col.f32.f16.f16.f32 "
        "{%0,%1,%2,%3},{%4,%5,%6,%7},{%8,%9},{%0,%1,%2,%3};"
        : "+f"(c[0]), "+f"(c[1]), "+f"(c[2]), "+f"(c[3])
        : "r"(a0), "r"(a1), "r"(a2), "r"(a3), "r"(b0), "r"(b1));
}

// ---------------------------------------------------------------------------
// fp16 tensor-core GEMM NT: C[M,N] = A[M,K] * B[N,K]^T  (A,B half, C fp32)
// Block 128x128, 4 warps, warp tile 64x64, BK=64 halves (128B/row), 2-stage.
// smem row stride 72 halves (36 u32) -> conflict-free fragment LDS.
// ---------------------------------------------------------------------------
#define HBM 128
#define HBN 128
#define HBK 64
#define HAST 36   // u32 per smem row (= 72 halves = 144 bytes)
#define GEMMH_SMEM (2 * (HBM + HBN) * HAST * 4)   // 73728 bytes

__global__ __launch_bounds__(128, 2) void gemm_f16(const __half* __restrict__ A,
                                                   const __half* __restrict__ B,
                                                   float* __restrict__ C,
                                                   int M, int N, int K)
{
    extern __shared__ char smraw[];
    const uint32_t sb = s2u(smraw);
    const uint32_t sA0 = sb;                          // [128][36] u32
    const uint32_t sB0 = sb +     HBM * HAST * 4;
    const uint32_t sA1 = sb + 2 * HBM * HAST * 4;
    const uint32_t sB1 = sb + 3 * HBM * HAST * 4;

    const int tid  = threadIdx.x;
    const int warp = tid >> 5;
    const int lane = tid & 31;
    const int wm = (warp >> 1) * 64;
    const int wn = (warp & 1) * 64;
    const int lr = lane >> 2;
    const int lc = lane & 3;

    const int m0 = blockIdx.y * HBM;
    const int n0 = blockIdx.x * HBN;

    // loader: rows tid>>3 (+16i), 16B chunk tid&7
    const int ldr = tid >> 3;          // 0..15
    const int ldch = (tid & 7) * 16;   // byte offset within 128B row

    const char* Ab = (const char*)(A + (size_t)m0 * K);
    const char* Bb = (const char*)(B + (size_t)n0 * K);

    float c[4][8][4];
    #pragma unroll
    for (int i = 0; i < 4; i++)
        #pragma unroll
        for (int j = 0; j < 8; j++)
            #pragma unroll
            for (int e = 0; e < 4; e++) c[i][j][e] = 0.f;

    const int nk = K / HBK;   // 32

    {
        #pragma unroll
        for (int i = 0; i < 8; i++) {
            int r = ldr + 16 * i;
            cpa16s(sA0 + r * 144 + ldch, Ab + (size_t)r * K * 2 + ldch);
            cpa16s(sB0 + r * 144 + ldch, Bb + (size_t)r * K * 2 + ldch);
        }
        asm volatile("cp.async.commit_group;");
    }

    for (int kt = 0; kt < nk; kt++) {
        asm volatile("cp.async.wait_group 0;");
        __syncthreads();

        if (kt + 1 < nk) {
            const size_t kb = (size_t)(kt + 1) * HBK * 2;
            const uint32_t dA = (kt + 1) & 1 ? sA1 : sA0;
            const uint32_t dB = (kt + 1) & 1 ? sB1 : sB0;
            #pragma unroll
            for (int i = 0; i < 8; i++) {
                int r = ldr + 16 * i;
                cpa16s(dA + r * 144 + ldch, Ab + (size_t)r * K * 2 + kb + ldch);
                cpa16s(dB + r * 144 + ldch, Bb + (size_t)r * K * 2 + kb + ldch);
            }
            asm volatile("cp.async.commit_group;");
        }

        const uint32_t* as_u = (const uint32_t*)(smraw + ((kt & 1) ? (2 * HBM * HAST * 4) : 0));
        const uint32_t* bs_u = as_u + HBM * HAST;

        #pragma unroll
        for (int ks = 0; ks < 4; ks++) {
            const int kk = ks * 8;   // u32 offset within row
            uint32_t a[4][4], b[8][2];
            #pragma unroll
            for (int mt = 0; mt < 4; mt++) {
                int base = (wm + mt * 16 + lr) * HAST + kk + lc;
                a[mt][0] = as_u[base];
                a[mt][1] = as_u[base + 8 * HAST];
                a[mt][2] = as_u[base + 4];
                a[mt][3] = as_u[base + 8 * HAST + 4];
            }
            #pragma unroll
            for (int nt = 0; nt < 8; nt++) {
                int base = (wn + nt * 8 + lr) * HAST + kk + lc;
                b[nt][0] = bs_u[base];
                b[nt][1] = bs_u[base + 4];
            }
            #pragma unroll
            for (int mt = 0; mt < 4; mt++)
                #pragma unroll
                for (int nt = 0; nt < 8; nt++)
                    mma_f16(c[mt][nt], a[mt][0], a[mt][1], a[mt][2], a[mt][3],
                            b[nt][0], b[nt][1]);
        }
    }

    #pragma unroll
    for (int mt = 0; mt < 4; mt++) {
        #pragma unroll
        for (int nt = 0; nt < 8; nt++) {
            int row = m0 + wm + mt * 16 + lr;
            int col = n0 + wn + nt * 8 + 2 * lc;
            *(float2*)(C + (size_t)row * N + col)       = make_float2(c[mt][nt][0], c[mt][nt][1]);
            *(float2*)(C + (size_t)(row + 8) * N + col) = make_float2(c[mt][nt][2], c[mt][nt][3]);
        }
    }
}

// ---------------------------------------------------------------------------
// RoPE, in place on Q and K (fp32)
// ---------------------------------------------------------------------------
__global__ void rope_kernel(float* __restrict__ Q, float* __restrict__ Kc)
{
    int idx = blockIdx.x * blockDim.x + threadIdx.x;
    if (idx >= MROWS * N_HEADS * 64) return;
    int j   = idx & 63;
    int h   = (idx >> 6) & (N_HEADS - 1);
    int row = idx >> 10;
    int s   = row & (SEQ - 1);

    float inv = exp2f(-(float)j * (13.287712379549449f / 64.0f));
    float ang = (float)s * inv;
    float sn, cs;
    sincosf(ang, &sn, &cs);

    size_t base = (size_t)row * D_MODEL + h * HEAD_DIM + j;
    float q1 = Q[base], q2 = Q[base + 64];
    Q[base]      = q1 * cs - q2 * sn;
    Q[base + 64] = q2 * cs + q1 * sn;
    float k1 = Kc[base], k2 = Kc[base + 64];
    Kc[base]      = k1 * cs - k2 * sn;
    Kc[base + 64] = k2 * cs + k1 * sn;
}

// ---------------------------------------------------------------------------
// Flash attention, tf32 mma.sync. 128 q-rows/block, 64-key tiles, 8 warps.
// Output written as fp16 (feeds fp16 out-projection).
// ---------------------------------------------------------------------------
#define AT_BM 128
#define AT_BK 64
#define QS_STR 132
#define KS_STR 132
#define VS_STR 136
#define PS_STR 68
#define ATTN_SMEM_BYTES ((AT_BM*QS_STR + AT_BK*KS_STR + AT_BK*VS_STR + AT_BM*PS_STR) * 4)

__global__ __launch_bounds__(256, 1) void attn_tf32(const float* __restrict__ Q,
                                                    const float* __restrict__ K,
                                                    const float* __restrict__ V,
                                                    __half* __restrict__ O)
{
    extern __shared__ float sm[];
    float* Qs = sm;                              // 128 x 132
    float* Ks = Qs + AT_BM * QS_STR;             // 64 x 132
    float* Vs = Ks + AT_BK * KS_STR;             // 64 x 136
    float* Ps = Vs + AT_BK * VS_STR;             // 128 x 68

    const int tid  = threadIdx.x;
    const int warp = tid >> 5;
    const int lane = tid & 31;
    const int lr = lane >> 2;
    const int lc = lane & 3;
    const int wm = warp * 16;

    const int q0 = blockIdx.x * AT_BM;
    const int b  = blockIdx.y >> 4;
    const int h  = blockIdx.y & (N_HEADS - 1);
    const float scale = 0.088388347648318447f;  // 1/sqrt(128)

    const float* Qb = Q + ((size_t)(b * SEQ + q0)) * D_MODEL + h * HEAD_DIM;
    const float* Kb = K + ((size_t)(b * SEQ)) * D_MODEL + h * HEAD_DIM;
    const float* Vb = V + ((size_t)(b * SEQ)) * D_MODEL + h * HEAD_DIM;

    for (int p = tid; p < AT_BM * 32; p += 256) {
        int r = p >> 5, d4 = (p & 31) << 2;
        float4 v = *(const float4*)(Qb + (size_t)r * D_MODEL + d4);
        float* dst = &Qs[r * QS_STR + d4];
        dst[0] = tf32r(v.x * scale); dst[1] = tf32r(v.y * scale);
        dst[2] = tf32r(v.z * scale); dst[3] = tf32r(v.w * scale);
    }

    float o_acc[16][4];
    #pragma unroll
    for (int i = 0; i < 16; i++)
        #pragma unroll
        for (int e = 0; e < 4; e++) o_acc[i][e] = 0.f;
    float m0 = -1e30f, m1 = -1e30f, l0 = 0.f, l1 = 0.f;

    const uint32_t* qs_u = (const uint32_t*)Qs;
    const uint32_t* ks_u = (const uint32_t*)Ks;
    const uint32_t* vs_u = (const uint32_t*)Vs;
    const uint32_t* ps_u = (const uint32_t*)Ps;

    const int r0g = q0 + wm + lr;
    const int r1g = r0g + 8;

    const int ntiles = 2 * blockIdx.x + 2;
    for (int kt = 0; kt < ntiles; kt++) {
        const int k0 = kt * AT_BK;
        __syncthreads();
        for (int p = tid; p < AT_BK * 32; p += 256) {
            int r = p >> 5, d4 = (p & 31) << 2;
            float4 kv = *(const float4*)(Kb + (size_t)(k0 + r) * D_MODEL + d4);
            float* kd = &Ks[r * KS_STR + d4];
            kd[0] = tf32r(kv.x); kd[1] = tf32r(kv.y);
            kd[2] = tf32r(kv.z); kd[3] = tf32r(kv.w);
            float4 vv = *(const float4*)(Vb + (size_t)(k0 + r) * D_MODEL + d4);
            float* vd = &Vs[r * VS_STR + d4];
            vd[0] = tf32r(vv.x); vd[1] = tf32r(vv.y);
            vd[2] = tf32r(vv.z); vd[3] = tf32r(vv.w);
        }
        __syncthreads();

        float s[8][4];
        #pragma unroll
        for (int nt = 0; nt < 8; nt++)
            #pragma unroll
            for (int e = 0; e < 4; e++) s[nt][e] = 0.f;

        #pragma unroll
        for (int ks = 0; ks < 16; ks++) {
            const int kk = ks * 8;
            int ab = (wm + lr) * QS_STR + kk + lc;
            uint32_t a0 = qs_u[ab];
            uint32_t a1 = qs_u[ab + 8 * QS_STR];
            uint32_t a2 = qs_u[ab + 4];
            uint32_t a3 = qs_u[ab + 8 * QS_STR + 4];
            #pragma unroll
            for (int nt = 0; nt < 8; nt++) {
                int bb = (nt * 8 + lr) * KS_STR + kk + lc;
                mma_tf32(s[nt], a0, a1, a2, a3, ks_u[bb], ks_u[bb + 4]);
            }
        }

        float rm0 = -1e30f, rm1 = -1e30f;
        #pragma unroll
        for (int nt = 0; nt < 8; nt++) {
            int c0 = k0 + nt * 8 + 2 * lc;
            if (c0     > r0g) s[nt][0] = -1e30f;
            if (c0 + 1 > r0g) s[nt][1] = -1e30f;
            if (c0     > r1g) s[nt][2] = -1e30f;
            if (c0 + 1 > r1g) s[nt][3] = -1e30f;
            rm0 = fmaxf(rm0, fmaxf(s[nt][0], s[nt][1]));
            rm1 = fmaxf(rm1, fmaxf(s[nt][2], s[nt][3]));
        }
        rm0 = fmaxf(rm0, __shfl_xor_sync(0xffffffffu, rm0, 1));
        rm0 = fmaxf(rm0, __shfl_xor_sync(0xffffffffu, rm0, 2));
        rm1 = fmaxf(rm1, __shfl_xor_sync(0xffffffffu, rm1, 1));
        rm1 = fmaxf(rm1, __shfl_xor_sync(0xffffffffu, rm1, 2));

        float mn0 = fmaxf(m0, rm0), mn1 = fmaxf(m1, rm1);
        float al0 = __expf(m0 - mn0), al1 = __expf(m1 - mn1);
        m0 = mn0; m1 = mn1;

        float ps0 = 0.f, ps1 = 0.f;
        #pragma unroll
        for (int nt = 0; nt < 8; nt++) {
            float p00 = __expf(s[nt][0] - mn0);
            float p01 = __expf(s[nt][1] - mn0);
            float p10 = __expf(s[nt][2] - mn1);
            float p11 = __expf(s[nt][3] - mn1);
            ps0 += p00 + p01;
            ps1 += p10 + p11;
            int pb = (wm + lr) * PS_STR + nt * 8 + 2 * lc;
            Ps[pb]     = tf32r(p00);
            Ps[pb + 1] = tf32r(p01);
            Ps[pb + 8 * PS_STR]     = tf32r(p10);
            Ps[pb + 8 * PS_STR + 1] = tf32r(p11);
        }
        ps0 += __shfl_xor_sync(0xffffffffu, ps0, 1);
        ps0 += __shfl_xor_sync(0xffffffffu, ps0, 2);
        ps1 += __shfl_xor_sync(0xffffffffu, ps1, 1);
        ps1 += __shfl_xor_sync(0xffffffffu, ps1, 2);
        l0 = l0 * al0 + ps0;
        l1 = l1 * al1 + ps1;

        #pragma unroll
        for (int nt2 = 0; nt2 < 16; nt2++) {
            o_acc[nt2][0] *= al0; o_acc[nt2][1] *= al0;
            o_acc[nt2][2] *= al1; o_acc[nt2][3] *= al1;
        }
        __syncwarp();

        #pragma unroll
        for (int ks = 0; ks < 8; ks++) {
            const int kk = ks * 8;
            int ab = (wm + lr) * PS_STR + kk + lc;
            uint32_t a0 = ps_u[ab];
            uint32_t a1 = ps_u[ab + 8 * PS_STR];
            uint32_t a2 = ps_u[ab + 4];
            uint32_t a3 = ps_u[ab + 8 * PS_STR + 4];
            #pragma unroll
            for (int nt2 = 0; nt2 < 16; nt2++) {
                int vb = (kk + lc) * VS_STR + nt2 * 8 + lr;
                mma_tf32(o_acc[nt2], a0, a1, a2, a3, vs_u[vb], vs_u[vb + 4 * VS_STR]);
            }
        }
        __syncwarp();
    }

    // epilogue: normalize, convert to fp16 (feeds fp16 out-projection)
    float inv0 = 1.0f / l0, inv1 = 1.0f / l1;
    __half* Ob = O + ((size_t)(b * SEQ + q0 + wm + lr)) * D_MODEL + h * HEAD_DIM;
    #pragma unroll
    for (int nt2 = 0; nt2 < 16; nt2++) {
        int col = nt2 * 8 + 2 * lc;
        *(__half2*)(Ob + col) = __floats2half2_rn(o_acc[nt2][0] * inv0,
                                                  o_acc[nt2][1] * inv0);
        *(__half2*)(Ob + 8 * D_MODEL + col) = __floats2half2_rn(o_acc[nt2][2] * inv1,
                                                                o_acc[nt2][3] * inv1);
    }
}

// ---------------------------------------------------------------------------
extern "C" void kernel_launch(void* const* d_in, const int* in_sizes, int n_in,
                              void* d_out, int out_size)
{
    const float* X  = (const float*)d_in[0];
    const float* Wq = (const float*)d_in[1];
    const float* Wk = (const float*)d_in[2];
    const float* Wv = (const float*)d_in[3];
    const float* Wo = (const float*)d_in[4];
    float* out = (float*)d_out;

    float *q, *k, *v;
    __half *xh, *oh, *wh;
    cudaGetSymbolAddress((void**)&q, g_q);
    cudaGetSymbolAddress((void**)&k, g_k);
    cudaGetSymbolAddress((void**)&v, g_v);
    cudaGetSymbolAddress((void**)&xh, g_xh);
    cudaGetSymbolAddress((void**)&oh, g_oh);
    cudaGetSymbolAddress((void**)&wh, g_wh);
    __half* wqh = wh;
    __half* wkh = wh + (size_t)D_MODEL * D_MODEL;
    __half* wvh = wh + 2 * (size_t)D_MODEL * D_MODEL;
    __half* woh = wh + 3 * (size_t)D_MODEL * D_MODEL;

    cudaFuncSetAttribute(attn_tf32, cudaFuncAttributeMaxDynamicSharedMemorySize,
                         ATTN_SMEM_BYTES);
    cudaFuncSetAttribute(gemm_f16, cudaFuncAttributeMaxDynamicSharedMemorySize,
                         GEMMH_SMEM);

    // 1) convert GEMM operands to fp16
    {
        int nx4 = (MROWS * D_MODEL) / 4;
        int nw4 = (D_MODEL * D_MODEL) / 4;
        f2h<<<(nx4 + 255) / 256, 256>>>((const float4*)X,  (uint2*)xh,  nx4);
        f2h<<<(nw4 + 255) / 256, 256>>>((const float4*)Wq, (uint2*)wqh, nw4);
        f2h<<<(nw4 + 255) / 256, 256>>>((const float4*)Wk, (uint2*)wkh, nw4);
        f2h<<<(nw4 + 255) / 256, 256>>>((const float4*)Wv, (uint2*)wvh, nw4);
        f2h<<<(nw4 + 255) / 256, 256>>>((const float4*)Wo, (uint2*)woh, nw4);
    }

    dim3 gg(D_MODEL / HBN, MROWS / HBM);   // 16 x 32
    dim3 blk(128);

    // 2) QKV projections (fp16 tensor cores, fp32 accumulate)
    gemm_f16<<<gg, blk, GEMMH_SMEM>>>(xh, wqh, q, MROWS, D_MODEL, D_MODEL);
    gemm_f16<<<gg, blk, GEMMH_SMEM>>>(xh, wkh, k, MROWS, D_MODEL, D_MODEL);
    gemm_f16<<<gg, blk, GEMMH_SMEM>>>(xh, wvh, v, MROWS, D_MODEL, D_MODEL);

    // 3) RoPE
    rope_kernel<<<(MROWS * N_HEADS * 64) / 256, 256>>>(q, k);

    // 4) attention (tf32 tensor cores, fp16 output)
    attn_tf32<<<dim3(SEQ / AT_BM, BATCH * N_HEADS), 256, ATTN_SMEM_BYTES>>>(q, k, v, oh);

    // 5) output projection (fp16)
    gemm_f16<<<gg, blk, GEMMH_SMEM>>>(oh, woh, out, MROWS, D_MODEL, D_MODEL);
}

// round 8
// speedup vs baseline: 5.7633x; 1.1440x over previous
#include <cuda_runtime.h>
#include <cuda_fp16.h>
#include <math.h>
#include <stdint.h>

#define D_MODEL 2048
#define N_HEADS 16
#define HEAD_DIM 128
#define SEQ 2048
#define BATCH 2
#define MROWS (BATCH*SEQ)   // 4096

// Scratch (static device globals; no allocation allowed)
__device__ float  g_q[(size_t)MROWS * D_MODEL];
__device__ float  g_k[(size_t)MROWS * D_MODEL];
__device__ float  g_v[(size_t)MROWS * D_MODEL];
__device__ __half g_qh[(size_t)MROWS * D_MODEL];
__device__ __half g_kh[(size_t)MROWS * D_MODEL];
__device__ __half g_vh[(size_t)MROWS * D_MODEL];
__device__ __half g_xh[(size_t)MROWS * D_MODEL];
__device__ __half g_oh[(size_t)MROWS * D_MODEL];
__device__ __half g_wh[4][(size_t)D_MODEL * D_MODEL];

// ---------------------------------------------------------------------------
// helpers
// ---------------------------------------------------------------------------
__global__ void f2h(const float4* __restrict__ src, uint2* __restrict__ dst, int n4)
{
    int i = blockIdx.x * blockDim.x + threadIdx.x;
    if (i >= n4) return;
    float4 v = src[i];
    __half2 h01 = __floats2half2_rn(v.x, v.y);
    __half2 h23 = __floats2half2_rn(v.z, v.w);
    dst[i] = make_uint2(*(uint32_t*)&h01, *(uint32_t*)&h23);
}

__device__ __forceinline__ void cpa16s(uint32_t saddr, const void* g) {
    asm volatile("cp.async.cg.shared.global [%0], [%1], 16;" :: "r"(saddr), "l"(g));
}

__device__ __forceinline__ uint32_t s2u(const void* p) {
    uint32_t a;
    asm("{ .reg .u64 t; cvta.to.shared.u64 t, %1; cvt.u32.u64 %0, t; }" : "=r"(a) : "l"(p));
    return a;
}

__device__ __forceinline__ void mma_f16(float* c,
                                        uint32_t a0, uint32_t a1, uint32_t a2, uint32_t a3,
                                        uint32_t b0, uint32_t b1)
{
    asm volatile(
        "mma.sync.aligned.m16n8k16.row.col.f32.f16.f16.f32 "
        "{%0,%1,%2,%3},{%4,%5,%6,%7},{%8,%9},{%0,%1,%2,%3};"
        : "+f"(c[0]), "+f"(c[1]), "+f"(c[2]), "+f"(c[3])
        : "r"(a0), "r"(a1), "r"(a2), "r"(a3), "r"(b0), "r"(b1));
}

#define LDSM_X4(R0,R1,R2,R3,ADDR) \
    asm volatile("ldmatrix.sync.aligned.m8n8.x4.shared.b16 {%0,%1,%2,%3}, [%4];" \
        : "=r"(R0), "=r"(R1), "=r"(R2), "=r"(R3) : "r"(ADDR))

#define LDSM_X4T(R0,R1,R2,R3,ADDR) \
    asm volatile("ldmatrix.sync.aligned.m8n8.x4.trans.shared.b16 {%0,%1,%2,%3}, [%4];" \
        : "=r"(R0), "=r"(R1), "=r"(R2), "=r"(R3) : "r"(ADDR))

// ---------------------------------------------------------------------------
// fp16 GEMM NT with ldmatrix: C[M,N] = A[M,K] * B[N,K]^T (A,B half, C fp32)
// Block 128x128, 4 warps (64x64 each), BK=64 halves (128B/row, stride 144B).
// ---------------------------------------------------------------------------
#define HBM 128
#define HBN 128
#define HBK 64
#define HROWB 144                       // bytes per smem row
#define GEMMH_SMEM (4 * HBM * HROWB)    // A0,B0,A1,B1 = 73728 bytes

__global__ __launch_bounds__(128, 2) void gemm_f16(const __half* __restrict__ A,
                                                   const __half* __restrict__ B,
                                                   float* __restrict__ C,
                                                   int M, int N, int K)
{
    extern __shared__ char smraw[];
    const uint32_t sb = s2u(smraw);

    const int tid  = threadIdx.x;
    const int warp = tid >> 5;
    const int lane = tid & 31;
    const int wm = (warp >> 1) * 64;
    const int wn = (warp & 1) * 64;
    const int lr = lane >> 2;
    const int lc = lane & 3;

    const int m0 = blockIdx.y * HBM;
    const int n0 = blockIdx.x * HBN;

    const int ldr  = tid >> 3;
    const int ldch = (tid & 7) * 16;

    const char* Ab = (const char*)(A + (size_t)m0 * K);
    const char* Bb = (const char*)(B + (size_t)n0 * K);

    // ldmatrix per-thread address offsets (bytes, within a buffer)
    uint32_t aOff[4], bOff[4];
    #pragma unroll
    for (int mt = 0; mt < 4; mt++)
        aOff[mt] = (wm + mt * 16 + (lane & 15)) * HROWB + ((lane & 16) ? 16 : 0);
    #pragma unroll
    for (int ntp = 0; ntp < 4; ntp++)
        bOff[ntp] = (wn + (2 * ntp + ((lane & 16) ? 1 : 0)) * 8 + (lane & 7)) * HROWB
                  + ((lane & 8) ? 16 : 0);

    float c[4][8][4];
    #pragma unroll
    for (int i = 0; i < 4; i++)
        #pragma unroll
        for (int j = 0; j < 8; j++)
            #pragma unroll
            for (int e = 0; e < 4; e++) c[i][j][e] = 0.f;

    const int nk = K / HBK;   // 32

    {
        #pragma unroll
        for (int i = 0; i < 8; i++) {
            int r = ldr + 16 * i;
            cpa16s(sb + r * HROWB + ldch,              Ab + (size_t)r * K * 2 + ldch);
            cpa16s(sb + HBM * HROWB + r * HROWB + ldch, Bb + (size_t)r * K * 2 + ldch);
        }
        asm volatile("cp.async.commit_group;");
    }

    for (int kt = 0; kt < nk; kt++) {
        asm volatile("cp.async.wait_group 0;");
        __syncthreads();

        if (kt + 1 < nk) {
            const size_t kb = (size_t)(kt + 1) * HBK * 2;
            const uint32_t dA = sb + (((kt + 1) & 1) ? 2 * HBM * HROWB : 0);
            const uint32_t dB = dA + HBM * HROWB;
            #pragma unroll
            for (int i = 0; i < 8; i++) {
                int r = ldr + 16 * i;
                cpa16s(dA + r * HROWB + ldch, Ab + (size_t)r * K * 2 + kb + ldch);
                cpa16s(dB + r * HROWB + ldch, Bb + (size_t)r * K * 2 + kb + ldch);
            }
            asm volatile("cp.async.commit_group;");
        }

        const uint32_t bufA = sb + ((kt & 1) ? 2 * HBM * HROWB : 0);
        const uint32_t bufB = bufA + HBM * HROWB;

        #pragma unroll
        for (int ks = 0; ks < 4; ks++) {
            uint32_t a[4][4], b[4][4];
            #pragma unroll
            for (int mt = 0; mt < 4; mt++)
                LDSM_X4(a[mt][0], a[mt][1], a[mt][2], a[mt][3],
                        bufA + aOff[mt] + ks * 32);
            #pragma unroll
            for (int ntp = 0; ntp < 4; ntp++)
                LDSM_X4(b[ntp][0], b[ntp][1], b[ntp][2], b[ntp][3],
                        bufB + bOff[ntp] + ks * 32);
            #pragma unroll
            for (int mt = 0; mt < 4; mt++)
                #pragma unroll
                for (int nt = 0; nt < 8; nt++)
                    mma_f16(c[mt][nt], a[mt][0], a[mt][1], a[mt][2], a[mt][3],
                            b[nt >> 1][(nt & 1) * 2], b[nt >> 1][(nt & 1) * 2 + 1]);
        }
    }

    #pragma unroll
    for (int mt = 0; mt < 4; mt++) {
        #pragma unroll
        for (int nt = 0; nt < 8; nt++) {
            int row = m0 + wm + mt * 16 + lr;
            int col = n0 + wn + nt * 8 + 2 * lc;
            *(float2*)(C + (size_t)row * N + col)       = make_float2(c[mt][nt][0], c[mt][nt][1]);
            *(float2*)(C + (size_t)(row + 8) * N + col) = make_float2(c[mt][nt][2], c[mt][nt][3]);
        }
    }
}

// ---------------------------------------------------------------------------
// Fused RoPE + fp16 convert: reads fp32 q,k,v; writes fp16 qh (pre-scaled),
// kh, vh.
// ---------------------------------------------------------------------------
__global__ void rope_f16(const float* __restrict__ Q, const float* __restrict__ K,
                         const float* __restrict__ V,
                         __half* __restrict__ Qh, __half* __restrict__ Kh,
                         __half* __restrict__ Vh)
{
    int idx = blockIdx.x * blockDim.x + threadIdx.x;
    if (idx >= MROWS * N_HEADS * 64) return;
    int j   = idx & 63;
    int h   = (idx >> 6) & (N_HEADS - 1);
    int row = idx >> 10;
    int s   = row & (SEQ - 1);

    float inv = exp2f(-(float)j * (13.287712379549449f / 64.0f));
    float ang = (float)s * inv;
    float sn, cs;
    sincosf(ang, &sn, &cs);
    const float scale = 0.088388347648318447f;  // 1/sqrt(128)

    size_t base = (size_t)row * D_MODEL + h * HEAD_DIM + j;
    float q1 = Q[base], q2 = Q[base + 64];
    Qh[base]      = __float2half((q1 * cs - q2 * sn) * scale);
    Qh[base + 64] = __float2half((q2 * cs + q1 * sn) * scale);
    float k1 = K[base], k2 = K[base + 64];
    Kh[base]      = __float2half(k1 * cs - k2 * sn);
    Kh[base + 64] = __float2half(k2 * cs + k1 * sn);
    Vh[base]      = __float2half(V[base]);
    Vh[base + 64] = __float2half(V[base + 64]);
}

// ---------------------------------------------------------------------------
// Flash attention, fp16 mma + ldmatrix. 128 q-rows/block, 64-key tiles, 8 warps.
// Qs/Ks/Vs stride 136 halves, Ps stride 72 halves (all ldmatrix conflict-free).
// ---------------------------------------------------------------------------
#define AT_BM 128
#define AT_BK 64
#define QSH 136
#define PSH 72
#define OFF_K (128*QSH)            // halves
#define OFF_V (OFF_K + 64*QSH)
#define OFF_P (OFF_V + 64*QSH)
#define ATTN_SMEM_BYTES ((OFF_P + 128*PSH) * 2)   // 88064

__global__ __launch_bounds__(256, 1) void attn_f16(const __half* __restrict__ Q,
                                                   const __half* __restrict__ K,
                                                   const __half* __restrict__ V,
                                                   __half* __restrict__ O)
{
    extern __shared__ char smraw[];
    __half* smh = (__half*)smraw;
    const uint32_t sb = s2u(smraw);
    const uint32_t sbQ = sb;
    const uint32_t sbK = sb + OFF_K * 2;
    const uint32_t sbV = sb + OFF_V * 2;
    const uint32_t sbP = sb + OFF_P * 2;

    const int tid  = threadIdx.x;
    const int warp = tid >> 5;
    const int lane = tid & 31;
    const int lr = lane >> 2;
    const int lc = lane & 3;
    const int wm = warp * 16;

    const int q0 = blockIdx.x * AT_BM;
    const int b  = blockIdx.y >> 4;
    const int h  = blockIdx.y & (N_HEADS - 1);

    const __half* Qb = Q + ((size_t)(b * SEQ + q0)) * D_MODEL + h * HEAD_DIM;
    const __half* Kb = K + ((size_t)(b * SEQ)) * D_MODEL + h * HEAD_DIM;
    const __half* Vb = V + ((size_t)(b * SEQ)) * D_MODEL + h * HEAD_DIM;

    // Load Q tile (fp16, pre-scaled by rope kernel)
    for (int p = tid; p < AT_BM * 16; p += 256) {
        int r = p >> 4, c = p & 15;
        uint4 v = *(const uint4*)(Qb + (size_t)r * D_MODEL + c * 8);
        *(uint4*)(smh + r * QSH + c * 8) = v;
    }

    // ldmatrix offsets (bytes)
    const uint32_t aQoff = ((wm + (lane & 15)) * QSH + ((lane & 16) ? 8 : 0)) * 2;
    uint32_t bKoff[4];
    #pragma unroll
    for (int ntp = 0; ntp < 4; ntp++)
        bKoff[ntp] = (((2 * ntp + ((lane & 16) ? 1 : 0)) * 8 + (lane & 7)) * QSH
                      + ((lane & 8) ? 8 : 0)) * 2;
    const uint32_t aPoff = ((wm + (lane & 15)) * PSH + ((lane & 16) ? 8 : 0)) * 2;
    uint32_t bVoff[8];
    #pragma unroll
    for (int ntp = 0; ntp < 8; ntp++)
        bVoff[ntp] = ((lane & 15) * QSH + (2 * ntp + ((lane & 16) ? 1 : 0)) * 8) * 2;

    float o_acc[16][4];
    #pragma unroll
    for (int i = 0; i < 16; i++)
        #pragma unroll
        for (int e = 0; e < 4; e++) o_acc[i][e] = 0.f;
    float m0 = -1e30f, m1 = -1e30f, l0 = 0.f, l1 = 0.f;

    const int r0g = q0 + wm + lr;
    const int r1g = r0g + 8;

    const int ntiles = 2 * blockIdx.x + 2;
    for (int kt = 0; kt < ntiles; kt++) {
        const int k0 = kt * AT_BK;
        __syncthreads();
        for (int p = tid; p < AT_BK * 16; p += 256) {
            int r = p >> 4, c = p & 15;
            uint4 kv = *(const uint4*)(Kb + (size_t)(k0 + r) * D_MODEL + c * 8);
            *(uint4*)(smh + OFF_K + r * QSH + c * 8) = kv;
            uint4 vv = *(const uint4*)(Vb + (size_t)(k0 + r) * D_MODEL + c * 8);
            *(uint4*)(smh + OFF_V + r * QSH + c * 8) = vv;
        }
        __syncthreads();

        // S = Q @ K^T (16x64 per warp), fp16 mma k16
        float s[8][4];
        #pragma unroll
        for (int nt = 0; nt < 8; nt++)
            #pragma unroll
            for (int e = 0; e < 4; e++) s[nt][e] = 0.f;

        #pragma unroll
        for (int ks = 0; ks < 8; ks++) {
            uint32_t a0, a1, a2, a3;
            LDSM_X4(a0, a1, a2, a3, sbQ + aQoff + ks * 32);
            #pragma unroll
            for (int ntp = 0; ntp < 4; ntp++) {
                uint32_t b0, b1, b2, b3;
                LDSM_X4(b0, b1, b2, b3, sbK + bKoff[ntp] + ks * 32);
                mma_f16(s[2 * ntp],     a0, a1, a2, a3, b0, b1);
                mma_f16(s[2 * ntp + 1], a0, a1, a2, a3, b2, b3);
            }
        }

        // mask + online softmax
        float rm0 = -1e30f, rm1 = -1e30f;
        #pragma unroll
        for (int nt = 0; nt < 8; nt++) {
            int c0 = k0 + nt * 8 + 2 * lc;
            if (c0     > r0g) s[nt][0] = -1e30f;
            if (c0 + 1 > r0g) s[nt][1] = -1e30f;
            if (c0     > r1g) s[nt][2] = -1e30f;
            if (c0 + 1 > r1g) s[nt][3] = -1e30f;
            rm0 = fmaxf(rm0, fmaxf(s[nt][0], s[nt][1]));
            rm1 = fmaxf(rm1, fmaxf(s[nt][2], s[nt][3]));
        }
        rm0 = fmaxf(rm0, __shfl_xor_sync(0xffffffffu, rm0, 1));
        rm0 = fmaxf(rm0, __shfl_xor_sync(0xffffffffu, rm0, 2));
        rm1 = fmaxf(rm1, __shfl_xor_sync(0xffffffffu, rm1, 1));
        rm1 = fmaxf(rm1, __shfl_xor_sync(0xffffffffu, rm1, 2));

        float mn0 = fmaxf(m0, rm0), mn1 = fmaxf(m1, rm1);
        float al0 = __expf(m0 - mn0), al1 = __expf(m1 - mn1);
        m0 = mn0; m1 = mn1;

        float ps0 = 0.f, ps1 = 0.f;
        uint32_t* Pw = (uint32_t*)(smh + OFF_P);
        #pragma unroll
        for (int nt = 0; nt < 8; nt++) {
            float p00 = __expf(s[nt][0] - mn0);
            float p01 = __expf(s[nt][1] - mn0);
            float p10 = __expf(s[nt][2] - mn1);
            float p11 = __expf(s[nt][3] - mn1);
            ps0 += p00 + p01;
            ps1 += p10 + p11;
            __half2 h0 = __floats2half2_rn(p00, p01);
            __half2 h1 = __floats2half2_rn(p10, p11);
            int pb = (wm + lr) * (PSH / 2) + nt * 4 + lc;
            Pw[pb]                    = *(uint32_t*)&h0;
            Pw[pb + 8 * (PSH / 2)]    = *(uint32_t*)&h1;
        }
        ps0 += __shfl_xor_sync(0xffffffffu, ps0, 1);
        ps0 += __shfl_xor_sync(0xffffffffu, ps0, 2);
        ps1 += __shfl_xor_sync(0xffffffffu, ps1, 1);
        ps1 += __shfl_xor_sync(0xffffffffu, ps1, 2);
        l0 = l0 * al0 + ps0;
        l1 = l1 * al1 + ps1;

        #pragma unroll
        for (int nt2 = 0; nt2 < 16; nt2++) {
            o_acc[nt2][0] *= al0; o_acc[nt2][1] *= al0;
            o_acc[nt2][2] *= al1; o_acc[nt2][3] *= al1;
        }
        __syncwarp();

        // O += P @ V (16x128 per warp); V b-fragments via ldmatrix.trans
        #pragma unroll
        for (int ks = 0; ks < 4; ks++) {
            uint32_t a0, a1, a2, a3;
            LDSM_X4(a0, a1, a2, a3, sbP + aPoff + ks * 32);
            #pragma unroll
            for (int ntp = 0; ntp < 8; ntp++) {
                uint32_t b0, b1, b2, b3;
                LDSM_X4T(b0, b1, b2, b3, sbV + bVoff[ntp] + ks * 16 * QSH * 2);
                mma_f16(o_acc[2 * ntp],     a0, a1, a2, a3, b0, b1);
                mma_f16(o_acc[2 * ntp + 1], a0, a1, a2, a3, b2, b3);
            }
        }
        __syncwarp();
    }

    // epilogue: normalize, convert to fp16 (feeds fp16 out-projection)
    float inv0 = 1.0f / l0, inv1 = 1.0f / l1;
    __half* Ob = O + ((size_t)(b * SEQ + q0 + wm + lr)) * D_MODEL + h * HEAD_DIM;
    #pragma unroll
    for (int nt2 = 0; nt2 < 16; nt2++) {
        int col = nt2 * 8 + 2 * lc;
        *(__half2*)(Ob + col) = __floats2half2_rn(o_acc[nt2][0] * inv0,
                                                  o_acc[nt2][1] * inv0);
        *(__half2*)(Ob + 8 * D_MODEL + col) = __floats2half2_rn(o_acc[nt2][2] * inv1,
                                                                o_acc[nt2][3] * inv1);
    }
}

// ---------------------------------------------------------------------------
extern "C" void kernel_launch(void* const* d_in, const int* in_sizes, int n_in,
                              void* d_out, int out_size)
{
    const float* X  = (const float*)d_in[0];
    const float* Wq = (const float*)d_in[1];
    const float* Wk = (const float*)d_in[2];
    const float* Wv = (const float*)d_in[3];
    const float* Wo = (const float*)d_in[4];
    float* out = (float*)d_out;

    float *q, *k, *v;
    __half *qh, *kh, *vh, *xh, *oh, *wh;
    cudaGetSymbolAddress((void**)&q, g_q);
    cudaGetSymbolAddress((void**)&k, g_k);
    cudaGetSymbolAddress((void**)&v, g_v);
    cudaGetSymbolAddress((void**)&qh, g_qh);
    cudaGetSymbolAddress((void**)&kh, g_kh);
    cudaGetSymbolAddress((void**)&vh, g_vh);
    cudaGetSymbolAddress((void**)&xh, g_xh);
    cudaGetSymbolAddress((void**)&oh, g_oh);
    cudaGetSymbolAddress((void**)&wh, g_wh);
    __half* wqh = wh;
    __half* wkh = wh + (size_t)D_MODEL * D_MODEL;
    __half* wvh = wh + 2 * (size_t)D_MODEL * D_MODEL;
    __half* woh = wh + 3 * (size_t)D_MODEL * D_MODEL;

    cudaFuncSetAttribute(attn_f16, cudaFuncAttributeMaxDynamicSharedMemorySize,
                         ATTN_SMEM_BYTES);
    cudaFuncSetAttribute(gemm_f16, cudaFuncAttributeMaxDynamicSharedMemorySize,
                         GEMMH_SMEM);

    // 1) convert GEMM operands to fp16
    {
        int nx4 = (MROWS * D_MODEL) / 4;
        int nw4 = (D_MODEL * D_MODEL) / 4;
        f2h<<<(nx4 + 255) / 256, 256>>>((const float4*)X,  (uint2*)xh,  nx4);
        f2h<<<(nw4 + 255) / 256, 256>>>((const float4*)Wq, (uint2*)wqh, nw4);
        f2h<<<(nw4 + 255) / 256, 256>>>((const float4*)Wk, (uint2*)wkh, nw4);
        f2h<<<(nw4 + 255) / 256, 256>>>((const float4*)Wv, (uint2*)wvh, nw4);
        f2h<<<(nw4 + 255) / 256, 256>>>((const float4*)Wo, (uint2*)woh, nw4);
    }

    dim3 gg(D_MODEL / HBN, MROWS / HBM);   // 16 x 32
    dim3 blk(128);

    // 2) QKV projections (fp16 mma + ldmatrix)
    gemm_f16<<<gg, blk, GEMMH_SMEM>>>(xh, wqh, q, MROWS, D_MODEL, D_MODEL);
    gemm_f16<<<gg, blk, GEMMH_SMEM>>>(xh, wkh, k, MROWS, D_MODEL, D_MODEL);
    gemm_f16<<<gg, blk, GEMMH_SMEM>>>(xh, wvh, v, MROWS, D_MODEL, D_MODEL);

    // 3) fused RoPE + fp16 conversion
    rope_f16<<<(MROWS * N_HEADS * 64) / 256, 256>>>(q, k, v, qh, kh, vh);

    // 4) attention (fp16 mma, ldmatrix, fp16 output)
    attn_f16<<<dim3(SEQ / AT_BM, BATCH * N_HEADS), 256, ATTN_SMEM_BYTES>>>(qh, kh, vh, oh);

    // 5) output projection (fp16)
    gemm_f16<<<gg, blk, GEMMH_SMEM>>>(oh, woh, out, MROWS, D_MODEL, D_MODEL);
}

// round 9
// speedup vs baseline: 7.6767x; 1.3320x over previous
#include <cuda_runtime.h>
#include <cuda_fp16.h>
#include <math.h>
#include <stdint.h>

#define D_MODEL 2048
#define N_HEADS 16
#define HEAD_DIM 128
#define SEQ 2048
#define BATCH 2
#define MROWS (BATCH*SEQ)   // 4096
#define NQKV (3*D_MODEL)    // 6144

// Scratch (static device globals; no allocation allowed)
__device__ __half g_qkvh[(size_t)MROWS * NQKV];           // fused QKV output (fp16)
__device__ __half g_qh[(size_t)MROWS * D_MODEL];
__device__ __half g_kh[(size_t)MROWS * D_MODEL];
__device__ __half g_vh[(size_t)MROWS * D_MODEL];
__device__ __half g_xh[(size_t)MROWS * D_MODEL];
__device__ __half g_oh[(size_t)MROWS * D_MODEL];
__device__ __half g_wh[4][(size_t)D_MODEL * D_MODEL];     // Wq,Wk,Wv contiguous; Wo

// ---------------------------------------------------------------------------
// helpers
// ---------------------------------------------------------------------------
__global__ void f2h(const float4* __restrict__ src, uint2* __restrict__ dst, int n4)
{
    int i = blockIdx.x * blockDim.x + threadIdx.x;
    if (i >= n4) return;
    float4 v = src[i];
    __half2 h01 = __floats2half2_rn(v.x, v.y);
    __half2 h23 = __floats2half2_rn(v.z, v.w);
    dst[i] = make_uint2(*(uint32_t*)&h01, *(uint32_t*)&h23);
}

__device__ __forceinline__ void cpa16s(uint32_t saddr, const void* g) {
    asm volatile("cp.async.cg.shared.global [%0], [%1], 16;" :: "r"(saddr), "l"(g));
}

__device__ __forceinline__ uint32_t s2u(const void* p) {
    uint32_t a;
    asm("{ .reg .u64 t; cvta.to.shared.u64 t, %1; cvt.u32.u64 %0, t; }" : "=r"(a) : "l"(p));
    return a;
}

__device__ __forceinline__ void mma_f16(float* c,
                                        uint32_t a0, uint32_t a1, uint32_t a2, uint32_t a3,
                                        uint32_t b0, uint32_t b1)
{
    asm volatile(
        "mma.sync.aligned.m16n8k16.row.col.f32.f16.f16.f32 "
        "{%0,%1,%2,%3},{%4,%5,%6,%7},{%8,%9},{%0,%1,%2,%3};"
        : "+f"(c[0]), "+f"(c[1]), "+f"(c[2]), "+f"(c[3])
        : "r"(a0), "r"(a1), "r"(a2), "r"(a3), "r"(b0), "r"(b1));
}

#define LDSM_X4(R0,R1,R2,R3,ADDR) \
    asm volatile("ldmatrix.sync.aligned.m8n8.x4.shared.b16 {%0,%1,%2,%3}, [%4];" \
        : "=r"(R0), "=r"(R1), "=r"(R2), "=r"(R3) : "r"(ADDR))

#define LDSM_X4T(R0,R1,R2,R3,ADDR) \
    asm volatile("ldmatrix.sync.aligned.m8n8.x4.trans.shared.b16 {%0,%1,%2,%3}, [%4];" \
        : "=r"(R0), "=r"(R1), "=r"(R2), "=r"(R3) : "r"(ADDR))

__device__ __forceinline__ uint32_t packh2(float a, float b) {
    __half2 h = __floats2half2_rn(a, b);
    return *(uint32_t*)&h;
}

// ---------------------------------------------------------------------------
// fp16 GEMM NT with ldmatrix: C[M,N] = A[M,K] * B[N,K]^T (A,B half)
// Block 128x128, 4 warps (64x64 each), BK=64 halves, 2-stage cp.async.
// ---------------------------------------------------------------------------
#define HBM 128
#define HBK 64
#define HROWB 144
#define GEMMH_SMEM (4 * HBM * HROWB)    // 73728 bytes

template<bool HALF_OUT>
__global__ __launch_bounds__(128, 2) void gemm_f16(const __half* __restrict__ A,
                                                   const __half* __restrict__ B,
                                                   void* __restrict__ Cv,
                                                   int M, int N, int K)
{
    extern __shared__ char smraw[];
    const uint32_t sb = s2u(smraw);

    const int tid  = threadIdx.x;
    const int warp = tid >> 5;
    const int lane = tid & 31;
    const int wm = (warp >> 1) * 64;
    const int wn = (warp & 1) * 64;
    const int lr = lane >> 2;
    const int lc = lane & 3;

    const int m0 = blockIdx.y * HBM;
    const int n0 = blockIdx.x * 128;

    const int ldr  = tid >> 3;
    const int ldch = (tid & 7) * 16;

    const char* Ab = (const char*)(A + (size_t)m0 * K);
    const char* Bb = (const char*)(B + (size_t)n0 * K);

    uint32_t aOff[4], bOff[4];
    #pragma unroll
    for (int mt = 0; mt < 4; mt++)
        aOff[mt] = (wm + mt * 16 + (lane & 15)) * HROWB + ((lane & 16) ? 16 : 0);
    #pragma unroll
    for (int ntp = 0; ntp < 4; ntp++)
        bOff[ntp] = (wn + (2 * ntp + ((lane & 16) ? 1 : 0)) * 8 + (lane & 7)) * HROWB
                  + ((lane & 8) ? 16 : 0);

    float c[4][8][4];
    #pragma unroll
    for (int i = 0; i < 4; i++)
        #pragma unroll
        for (int j = 0; j < 8; j++)
            #pragma unroll
            for (int e = 0; e < 4; e++) c[i][j][e] = 0.f;

    const int nk = K / HBK;

    {
        #pragma unroll
        for (int i = 0; i < 8; i++) {
            int r = ldr + 16 * i;
            cpa16s(sb + r * HROWB + ldch,               Ab + (size_t)r * K * 2 + ldch);
            cpa16s(sb + HBM * HROWB + r * HROWB + ldch, Bb + (size_t)r * K * 2 + ldch);
        }
        asm volatile("cp.async.commit_group;");
    }

    for (int kt = 0; kt < nk; kt++) {
        asm volatile("cp.async.wait_group 0;");
        __syncthreads();

        if (kt + 1 < nk) {
            const size_t kb = (size_t)(kt + 1) * HBK * 2;
            const uint32_t dA = sb + (((kt + 1) & 1) ? 2 * HBM * HROWB : 0);
            const uint32_t dB = dA + HBM * HROWB;
            #pragma unroll
            for (int i = 0; i < 8; i++) {
                int r = ldr + 16 * i;
                cpa16s(dA + r * HROWB + ldch, Ab + (size_t)r * K * 2 + kb + ldch);
                cpa16s(dB + r * HROWB + ldch, Bb + (size_t)r * K * 2 + kb + ldch);
            }
            asm volatile("cp.async.commit_group;");
        }

        const uint32_t bufA = sb + ((kt & 1) ? 2 * HBM * HROWB : 0);
        const uint32_t bufB = bufA + HBM * HROWB;

        #pragma unroll
        for (int ks = 0; ks < 4; ks++) {
            uint32_t a[4][4], b[4][4];
            #pragma unroll
            for (int mt = 0; mt < 4; mt++)
                LDSM_X4(a[mt][0], a[mt][1], a[mt][2], a[mt][3],
                        bufA + aOff[mt] + ks * 32);
            #pragma unroll
            for (int ntp = 0; ntp < 4; ntp++)
                LDSM_X4(b[ntp][0], b[ntp][1], b[ntp][2], b[ntp][3],
                        bufB + bOff[ntp] + ks * 32);
            #pragma unroll
            for (int mt = 0; mt < 4; mt++)
                #pragma unroll
                for (int nt = 0; nt < 8; nt++)
                    mma_f16(c[mt][nt], a[mt][0], a[mt][1], a[mt][2], a[mt][3],
                            b[nt >> 1][(nt & 1) * 2], b[nt >> 1][(nt & 1) * 2 + 1]);
        }
    }

    #pragma unroll
    for (int mt = 0; mt < 4; mt++) {
        #pragma unroll
        for (int nt = 0; nt < 8; nt++) {
            int row = m0 + wm + mt * 16 + lr;
            int col = n0 + wn + nt * 8 + 2 * lc;
            if (HALF_OUT) {
                __half* C = (__half*)Cv;
                *(uint32_t*)(C + (size_t)row * N + col)       = packh2(c[mt][nt][0], c[mt][nt][1]);
                *(uint32_t*)(C + (size_t)(row + 8) * N + col) = packh2(c[mt][nt][2], c[mt][nt][3]);
            } else {
                float* C = (float*)Cv;
                *(float2*)(C + (size_t)row * N + col)       = make_float2(c[mt][nt][0], c[mt][nt][1]);
                *(float2*)(C + (size_t)(row + 8) * N + col) = make_float2(c[mt][nt][2], c[mt][nt][3]);
            }
        }
    }
}

// ---------------------------------------------------------------------------
// Fused RoPE: reads fp16 fused qkv [MROWS][6144]; writes qh (pre-scaled), kh, vh.
// ---------------------------------------------------------------------------
__global__ void rope_f16(const __half* __restrict__ QKV,
                         __half* __restrict__ Qh, __half* __restrict__ Kh,
                         __half* __restrict__ Vh)
{
    int idx = blockIdx.x * blockDim.x + threadIdx.x;
    if (idx >= MROWS * N_HEADS * 64) return;
    int j   = idx & 63;
    int h   = (idx >> 6) & (N_HEADS - 1);
    int row = idx >> 10;
    int s   = row & (SEQ - 1);

    float inv = exp2f(-(float)j * (13.287712379549449f / 64.0f));
    float ang = (float)s * inv;
    float sn, cs;
    sincosf(ang, &sn, &cs);
    const float scale = 0.088388347648318447f;  // 1/sqrt(128)

    size_t bin  = (size_t)row * NQKV + h * HEAD_DIM + j;
    size_t bout = (size_t)row * D_MODEL + h * HEAD_DIM + j;

    float q1 = __half2float(QKV[bin]),            q2 = __half2float(QKV[bin + 64]);
    Qh[bout]      = __float2half((q1 * cs - q2 * sn) * scale);
    Qh[bout + 64] = __float2half((q2 * cs + q1 * sn) * scale);
    float k1 = __half2float(QKV[bin + D_MODEL]),  k2 = __half2float(QKV[bin + D_MODEL + 64]);
    Kh[bout]      = __float2half(k1 * cs - k2 * sn);
    Kh[bout + 64] = __float2half(k2 * cs + k1 * sn);
    Vh[bout]      = QKV[bin + 2 * D_MODEL];
    Vh[bout + 64] = QKV[bin + 2 * D_MODEL + 64];
}

// ---------------------------------------------------------------------------
// Flash attention, fp16 mma. 128 q-rows/block, 64-key tiles, 8 warps.
// cp.async double-buffered K/V; Q-fragments register-resident; P in registers.
// ---------------------------------------------------------------------------
#define QSH 136
#define OFF_Q  0
#define OFF_KV (128*QSH)                   // start of K/V buffers (halves)
#define KVBUF  (64*QSH)                    // one K or V buffer
#define ATTN_SMEM_BYTES ((128*QSH + 4*KVBUF) * 2)   // 104448

__global__ __launch_bounds__(256, 1) void attn_f16(const __half* __restrict__ Q,
                                                   const __half* __restrict__ K,
                                                   const __half* __restrict__ V,
                                                   __half* __restrict__ O)
{
    extern __shared__ char smraw[];
    const uint32_t sb = s2u(smraw);

    const int tid  = threadIdx.x;
    const int warp = tid >> 5;
    const int lane = tid & 31;
    const int lr = lane >> 2;
    const int lc = lane & 3;
    const int wm = warp * 16;

    const int qx = gridDim.x - 1 - blockIdx.x;   // heavy CTAs first
    const int q0 = qx * 128;
    const int b  = blockIdx.y >> 4;
    const int h  = blockIdx.y & (N_HEADS - 1);

    const __half* Qb = Q + ((size_t)(b * SEQ + q0)) * D_MODEL + h * HEAD_DIM;
    const __half* Kb = K + ((size_t)(b * SEQ)) * D_MODEL + h * HEAD_DIM;
    const __half* Vb = V + ((size_t)(b * SEQ)) * D_MODEL + h * HEAD_DIM;

    // ldmatrix offsets (bytes within a buffer)
    const uint32_t aQoff = ((wm + (lane & 15)) * QSH + ((lane & 16) ? 8 : 0)) * 2;
    uint32_t bKoff[4];
    #pragma unroll
    for (int ntp = 0; ntp < 4; ntp++)
        bKoff[ntp] = (((2 * ntp + ((lane & 16) ? 1 : 0)) * 8 + (lane & 7)) * QSH
                      + ((lane & 8) ? 8 : 0)) * 2;
    uint32_t bVoff[8];
    #pragma unroll
    for (int ntp = 0; ntp < 8; ntp++)
        bVoff[ntp] = ((lane & 15) * QSH + (2 * ntp + ((lane & 16) ? 1 : 0)) * 8) * 2;

    // prologue: cp.async Q + K0/V0
    {
        #pragma unroll
        for (int i = 0; i < 8; i++) {
            int p = tid + 256 * i;
            int r = p >> 4, ch = p & 15;
            cpa16s(sb + (OFF_Q + r * QSH) * 2 + ch * 16, Qb + (size_t)r * D_MODEL + ch * 8);
        }
        #pragma unroll
        for (int i = 0; i < 4; i++) {
            int p = tid + 256 * i;
            int r = p >> 4, ch = p & 15;
            cpa16s(sb + (OFF_KV + r * QSH) * 2 + ch * 16,         Kb + (size_t)r * D_MODEL + ch * 8);
            cpa16s(sb + (OFF_KV + KVBUF + r * QSH) * 2 + ch * 16, Vb + (size_t)r * D_MODEL + ch * 8);
        }
        asm volatile("cp.async.commit_group;");
    }

    uint32_t qf[8][4];
    float o_acc[16][4];
    #pragma unroll
    for (int i = 0; i < 16; i++)
        #pragma unroll
        for (int e = 0; e < 4; e++) o_acc[i][e] = 0.f;
    float m0 = -1e30f, m1 = -1e30f, l0 = 0.f, l1 = 0.f;

    const int r0g = q0 + wm + lr;
    const int r1g = r0g + 8;

    const int ntiles = 2 * qx + 2;
    for (int kt = 0; kt < ntiles; kt++) {
        asm volatile("cp.async.wait_group 0;");
        __syncthreads();

        if (kt == 0) {
            #pragma unroll
            for (int ks = 0; ks < 8; ks++)
                LDSM_X4(qf[ks][0], qf[ks][1], qf[ks][2], qf[ks][3],
                        sb + aQoff + ks * 32);
        }

        if (kt + 1 < ntiles) {
            const int nb = (kt + 1) & 1;
            const uint32_t dK = sb + (OFF_KV + nb * 2 * KVBUF) * 2;
            const uint32_t dV = dK + KVBUF * 2;
            const size_t krow = (size_t)(kt + 1) * 64;
            #pragma unroll
            for (int i = 0; i < 4; i++) {
                int p = tid + 256 * i;
                int r = p >> 4, ch = p & 15;
                cpa16s(dK + (r * QSH) * 2 + ch * 16, Kb + (krow + r) * D_MODEL + ch * 8);
                cpa16s(dV + (r * QSH) * 2 + ch * 16, Vb + (krow + r) * D_MODEL + ch * 8);
            }
            asm volatile("cp.async.commit_group;");
        }

        const uint32_t bufK = sb + (OFF_KV + (kt & 1) * 2 * KVBUF) * 2;
        const uint32_t bufV = bufK + KVBUF * 2;
        const int k0 = kt * 64;

        // S = Q @ K^T
        float s[8][4];
        #pragma unroll
        for (int nt = 0; nt < 8; nt++)
            #pragma unroll
            for (int e = 0; e < 4; e++) s[nt][e] = 0.f;

        #pragma unroll
        for (int ks = 0; ks < 8; ks++) {
            #pragma unroll
            for (int ntp = 0; ntp < 4; ntp++) {
                uint32_t b0, b1, b2, b3;
                LDSM_X4(b0, b1, b2, b3, bufK + bKoff[ntp] + ks * 32);
                mma_f16(s[2 * ntp],     qf[ks][0], qf[ks][1], qf[ks][2], qf[ks][3], b0, b1);
                mma_f16(s[2 * ntp + 1], qf[ks][0], qf[ks][1], qf[ks][2], qf[ks][3], b2, b3);
            }
        }

        // mask + online softmax
        float rm0 = -1e30f, rm1 = -1e30f;
        #pragma unroll
        for (int nt = 0; nt < 8; nt++) {
            int c0 = k0 + nt * 8 + 2 * lc;
            if (c0     > r0g) s[nt][0] = -1e30f;
            if (c0 + 1 > r0g) s[nt][1] = -1e30f;
            if (c0     > r1g) s[nt][2] = -1e30f;
            if (c0 + 1 > r1g) s[nt][3] = -1e30f;
            rm0 = fmaxf(rm0, fmaxf(s[nt][0], s[nt][1]));
            rm1 = fmaxf(rm1, fmaxf(s[nt][2], s[nt][3]));
        }
        rm0 = fmaxf(rm0, __shfl_xor_sync(0xffffffffu, rm0, 1));
        rm0 = fmaxf(rm0, __shfl_xor_sync(0xffffffffu, rm0, 2));
        rm1 = fmaxf(rm1, __shfl_xor_sync(0xffffffffu, rm1, 1));
        rm1 = fmaxf(rm1, __shfl_xor_sync(0xffffffffu, rm1, 2));

        float mn0 = fmaxf(m0, rm0), mn1 = fmaxf(m1, rm1);
        float al0 = __expf(m0 - mn0), al1 = __expf(m1 - mn1);
        m0 = mn0; m1 = mn1;

        float ps0 = 0.f, ps1 = 0.f;
        uint32_t pa[8], pb[8];   // P fragments: pa = row lr, pb = row lr+8
        #pragma unroll
        for (int nt = 0; nt < 8; nt++) {
            float p00 = __expf(s[nt][0] - mn0);
            float p01 = __expf(s[nt][1] - mn0);
            float p10 = __expf(s[nt][2] - mn1);
            float p11 = __expf(s[nt][3] - mn1);
            ps0 += p00 + p01;
            ps1 += p10 + p11;
            pa[nt] = packh2(p00, p01);
            pb[nt] = packh2(p10, p11);
        }
        ps0 += __shfl_xor_sync(0xffffffffu, ps0, 1);
        ps0 += __shfl_xor_sync(0xffffffffu, ps0, 2);
        ps1 += __shfl_xor_sync(0xffffffffu, ps1, 1);
        ps1 += __shfl_xor_sync(0xffffffffu, ps1, 2);
        l0 = l0 * al0 + ps0;
        l1 = l1 * al1 + ps1;

        #pragma unroll
        for (int nt2 = 0; nt2 < 16; nt2++) {
            o_acc[nt2][0] *= al0; o_acc[nt2][1] *= al0;
            o_acc[nt2][2] *= al1; o_acc[nt2][3] *= al1;
        }

        // O += P @ V (P in registers; V b-fragments via ldmatrix.trans)
        #pragma unroll
        for (int j = 0; j < 4; j++) {
            uint32_t a0 = pa[2 * j],     a1 = pb[2 * j];
            uint32_t a2 = pa[2 * j + 1], a3 = pb[2 * j + 1];
            #pragma unroll
            for (int ntp = 0; ntp < 8; ntp++) {
                uint32_t b0, b1, b2, b3;
                LDSM_X4T(b0, b1, b2, b3, bufV + bVoff[ntp] + j * 16 * QSH * 2);
                mma_f16(o_acc[2 * ntp],     a0, a1, a2, a3, b0, b1);
                mma_f16(o_acc[2 * ntp + 1], a0, a1, a2, a3, b2, b3);
            }
        }
    }

    // epilogue: normalize, fp16 out (feeds fp16 out-projection)
    float inv0 = 1.0f / l0, inv1 = 1.0f / l1;
    __half* Ob = O + ((size_t)(b * SEQ + q0 + wm + lr)) * D_MODEL + h * HEAD_DIM;
    #pragma unroll
    for (int nt2 = 0; nt2 < 16; nt2++) {
        int col = nt2 * 8 + 2 * lc;
        *(uint32_t*)(Ob + col)               = packh2(o_acc[nt2][0] * inv0, o_acc[nt2][1] * inv0);
        *(uint32_t*)(Ob + 8 * D_MODEL + col) = packh2(o_acc[nt2][2] * inv1, o_acc[nt2][3] * inv1);
    }
}

// ---------------------------------------------------------------------------
extern "C" void kernel_launch(void* const* d_in, const int* in_sizes, int n_in,
                              void* d_out, int out_size)
{
    const float* X  = (const float*)d_in[0];
    const float* Wq = (const float*)d_in[1];
    const float* Wk = (const float*)d_in[2];
    const float* Wv = (const float*)d_in[3];
    const float* Wo = (const float*)d_in[4];
    float* out = (float*)d_out;

    __half *qkvh, *qh, *kh, *vh, *xh, *oh, *wh;
    cudaGetSymbolAddress((void**)&qkvh, g_qkvh);
    cudaGetSymbolAddress((void**)&qh, g_qh);
    cudaGetSymbolAddress((void**)&kh, g_kh);
    cudaGetSymbolAddress((void**)&vh, g_vh);
    cudaGetSymbolAddress((void**)&xh, g_xh);
    cudaGetSymbolAddress((void**)&oh, g_oh);
    cudaGetSymbolAddress((void**)&wh, g_wh);
    __half* woh = wh + 3 * (size_t)D_MODEL * D_MODEL;

    cudaFuncSetAttribute(attn_f16, cudaFuncAttributeMaxDynamicSharedMemorySize,
                         ATTN_SMEM_BYTES);
    cudaFuncSetAttribute(gemm_f16<true>, cudaFuncAttributeMaxDynamicSharedMemorySize,
                         GEMMH_SMEM);
    cudaFuncSetAttribute(gemm_f16<false>, cudaFuncAttributeMaxDynamicSharedMemorySize,
                         GEMMH_SMEM);

    // 1) convert operands to fp16 (Wq,Wk,Wv land contiguously in g_wh)
    {
        int nx4 = (MROWS * D_MODEL) / 4;
        int nw4 = (D_MODEL * D_MODEL) / 4;
        f2h<<<(nx4 + 255) / 256, 256>>>((const float4*)X,  (uint2*)xh, nx4);
        f2h<<<(nw4 + 255) / 256, 256>>>((const float4*)Wq, (uint2*)wh, nw4);
        f2h<<<(nw4 + 255) / 256, 256>>>((const float4*)Wk, (uint2*)(wh + (size_t)D_MODEL*D_MODEL), nw4);
        f2h<<<(nw4 + 255) / 256, 256>>>((const float4*)Wv, (uint2*)(wh + 2*(size_t)D_MODEL*D_MODEL), nw4);
        f2h<<<(nw4 + 255) / 256, 256>>>((const float4*)Wo, (uint2*)woh, nw4);
    }

    // 2) fused QKV projection (one GEMM, N=6144, fp16 out)
    gemm_f16<true><<<dim3(NQKV / 128, MROWS / HBM), 128, GEMMH_SMEM>>>(
        xh, wh, qkvh, MROWS, NQKV, D_MODEL);

    // 3) fused RoPE (+ Q pre-scale) from fp16 qkv
    rope_f16<<<(MROWS * N_HEADS * 64) / 256, 256>>>(qkvh, qh, kh, vh);

    // 4) attention (fp16 mma, cp.async pipelined, register P)
    attn_f16<<<dim3(SEQ / 128, BATCH * N_HEADS), 256, ATTN_SMEM_BYTES>>>(qh, kh, vh, oh);

    // 5) output projection (fp32 out)
    gemm_f16<false><<<dim3(D_MODEL / 128, MROWS / HBM), 128, GEMMH_SMEM>>>(
        oh, woh, out, MROWS, D_MODEL, D_MODEL);
}